// round 1
// baseline (speedup 1.0000x reference)
#include <cuda_runtime.h>
#include <math.h>

#define NNODES 1024
#define NSPLIT2 64      // src splits in pass 2
#define SRC_PER_CTA2 (NNODES / NSPLIT2)   // 16

#define STEPF       (5.0f/9.0f)
#define INV_STEPF   1.8f
#define SQRT3F      1.7320508075688772f
#define INV_SQRT3F  0.5773502691896258f
#define INV_SQRT8F  0.35355339059327373f
#define INV_SQRT32F 0.17677669529663687f
#define INV_NNF     0.031265284f          /* 1/sqrt(1023) */

__device__ float g_xl  [NNODES*8];
__device__ float g_sc  [NNODES*32];
__device__ float g_m0  [NNODES*8];
__device__ float g_m1  [NNODES*24];
__device__ float g_scv [NNODES*3];
__device__ float g_a0n [NNODES*16];
__device__ float g_a1n [NNODES*48];
__device__ float g_pqrs[NNODES*800];
__device__ float g_part[NSPLIT2*NNODES*4];

__device__ __forceinline__ float siluf(float a) {
    return __fdividef(a, 1.0f + __expf(-a));
}
__device__ __forceinline__ float sigf(float a) {
    return __fdividef(1.0f, 1.0f + __expf(-a));
}

// ---------------------------------------------------------------------------
// Kernel A: per-node premix  xl = x@lin1a_w/sqrt(8), sc = x@sc1_w/sqrt(8)
// ---------------------------------------------------------------------------
__global__ void k_node_pre(const float* __restrict__ x,
                           const float* __restrict__ lin1a_w,
                           const float* __restrict__ sc1_w)
{
    int n = blockIdx.x * blockDim.x + threadIdx.x;
    if (n >= NNODES) return;
    float xr[8];
#pragma unroll
    for (int k = 0; k < 8; k++) xr[k] = x[n*8 + k];
#pragma unroll
    for (int u = 0; u < 8; u++) {
        float a = 0.f;
#pragma unroll
        for (int k = 0; k < 8; k++) a += xr[k] * __ldg(&lin1a_w[k*8 + u]);
        g_xl[n*8 + u] = a * INV_SQRT8F;
    }
#pragma unroll
    for (int j = 0; j < 32; j++) {
        float a = 0.f;
#pragma unroll
        for (int k = 0; k < 8; k++) a += xr[k] * __ldg(&sc1_w[k*32 + j]);
        g_sc[n*32 + j] = a * INV_SQRT8F;
    }
}

// ---------------------------------------------------------------------------
// Kernel B: pass 1 over all (dst, src) pairs. One CTA per dst.
// Computes m0[d][8], m1[d][8][3] (with inv_nn folded in).
// ---------------------------------------------------------------------------
__global__ void __launch_bounds__(256, 2)
k_pass1(const float* __restrict__ pos,
        const float* __restrict__ fc1_w1,
        const float* __restrict__ fc1_w2)
{
    __shared__ float w1t[100*12];   // transposed fc1_w1: [i][k], padded to 12
    __shared__ float w2s[100*16];   // fc1_w2 * 0.1
    __shared__ float cross[8*32];

    const int tid = threadIdx.x;
    const int d   = blockIdx.x;

    for (int idx = tid; idx < 1000; idx += 256) {
        int k = idx / 100, i = idx - k*100;
        w1t[i*12 + k] = fc1_w1[idx];
    }
    for (int idx = tid; idx < 1600; idx += 256)
        w2s[idx] = fc1_w2[idx] * 0.1f;

    const float pdx = pos[d*3+0], pdy = pos[d*3+1], pdz = pos[d*3+2];

    float acc[32];
#pragma unroll
    for (int j = 0; j < 32; j++) acc[j] = 0.f;

    __syncthreads();

    for (int s = tid; s < NNODES; s += 256) {
        if (s == d) continue;
        float vx = pos[s*3+0] - pdx;
        float vy = pos[s*3+1] - pdy;
        float vz = pos[s*3+2] - pdz;
        float r2 = vx*vx + vy*vy + vz*vz;
        float inv_r = rsqrtf(r2);
        float rr = (r2 * inv_r) * INV_STEPF;   // r/step

        float g[10];
#pragma unroll
        for (int k = 0; k < 10; k++) {
            float t = rr - (float)k;
            g[k] = __expf(-t*t);
        }

        float w[16];
#pragma unroll
        for (int u = 0; u < 16; u++) w[u] = 0.f;

#pragma unroll 2
        for (int i = 0; i < 100; i++) {
            const float4 wa = *(const float4*)&w1t[i*12];
            const float4 wb = *(const float4*)&w1t[i*12 + 4];
            const float2 wc = *(const float2*)&w1t[i*12 + 8];
            float a = g[0]*wa.x + g[1]*wa.y + g[2]*wa.z + g[3]*wa.w
                    + g[4]*wb.x + g[5]*wb.y + g[6]*wb.z + g[7]*wb.w
                    + g[8]*wc.x + g[9]*wc.y;
            float h = siluf(a);
            const float4 u0 = *(const float4*)&w2s[i*16];
            const float4 u1 = *(const float4*)&w2s[i*16 + 4];
            const float4 u2 = *(const float4*)&w2s[i*16 + 8];
            const float4 u3 = *(const float4*)&w2s[i*16 + 12];
            w[0]  += h*u0.x; w[1]  += h*u0.y; w[2]  += h*u0.z; w[3]  += h*u0.w;
            w[4]  += h*u1.x; w[5]  += h*u1.y; w[6]  += h*u1.z; w[7]  += h*u1.w;
            w[8]  += h*u2.x; w[9]  += h*u2.y; w[10] += h*u2.z; w[11] += h*u2.w;
            w[12] += h*u3.x; w[13] += h*u3.y; w[14] += h*u3.z; w[15] += h*u3.w;
        }

        const float4 xa = *(const float4*)&g_xl[s*8];
        const float4 xb = *(const float4*)&g_xl[s*8 + 4];
        float xl[8] = {xa.x, xa.y, xa.z, xa.w, xb.x, xb.y, xb.z, xb.w};

        float sy = SQRT3F * inv_r;
        float y0 = vx*sy, y1 = vy*sy, y2 = vz*sy;

#pragma unroll
        for (int u = 0; u < 8; u++) acc[u] += w[u] * xl[u];
#pragma unroll
        for (int u = 0; u < 8; u++) {
            float t = w[8+u] * xl[u];
            acc[8 + u*3 + 0] += t*y0;
            acc[8 + u*3 + 1] += t*y1;
            acc[8 + u*3 + 2] += t*y2;
        }
    }

    // block reduction of 32 accumulators over 256 threads
    const int lane = tid & 31, wid = tid >> 5;
#pragma unroll
    for (int j = 0; j < 32; j++) {
        float v = acc[j];
#pragma unroll
        for (int o = 16; o > 0; o >>= 1)
            v += __shfl_xor_sync(0xffffffffu, v, o);
        acc[j] = v;
    }
    if (lane == 0) {
#pragma unroll
        for (int j = 0; j < 32; j++) cross[wid*32 + j] = acc[j];
    }
    __syncthreads();
    if (tid < 32) {
        float sum = 0.f;
#pragma unroll
        for (int wi = 0; wi < 8; wi++) sum += cross[wi*32 + tid];
        sum *= INV_NNF;
        if (tid < 8) g_m0[d*8 + tid] = sum;
        else         g_m1[d*24 + (tid - 8)] = sum;
    }
}

// ---------------------------------------------------------------------------
// Kernel C: node middle stage -> scv, a0n, a1n
// ---------------------------------------------------------------------------
__global__ void k_node_mid(const float* __restrict__ lin2a0,
                           const float* __restrict__ lin2a1,
                           const float* __restrict__ alpha1_w,
                           const float* __restrict__ sc2_w,
                           const float* __restrict__ lin1b0,
                           const float* __restrict__ lin1b1)
{
    int n = blockIdx.x * blockDim.x + threadIdx.x;
    if (n >= NNODES) return;

    float m0[8], m1[24];
#pragma unroll
    for (int u = 0; u < 8; u++)  m0[u] = g_m0[n*8 + u];
#pragma unroll
    for (int j = 0; j < 24; j++) m1[j] = g_m1[n*24 + j];

    float alpha = 0.f;
#pragma unroll
    for (int u = 0; u < 8; u++) alpha += m0[u] * __ldg(&alpha1_w[u]);
    alpha *= INV_SQRT8F;

    float x0[16], gt[16];
#pragma unroll
    for (int j = 0; j < 32; j++) {
        float o = 0.f;
#pragma unroll
        for (int u = 0; u < 8; u++) o += m0[u] * __ldg(&lin2a0[u*32 + j]);
        float sv = g_sc[n*32 + j] + alpha * (o * INV_SQRT8F);
        if (j < 16) x0[j] = siluf(sv);
        else        gt[j - 16] = sigf(sv);
    }

    float x1[48];
#pragma unroll
    for (int v = 0; v < 16; v++) {
        float o0 = 0.f, o1 = 0.f, o2 = 0.f;
#pragma unroll
        for (int u = 0; u < 8; u++) {
            float lw = __ldg(&lin2a1[u*16 + v]);
            o0 += m1[u*3 + 0] * lw;
            o1 += m1[u*3 + 1] * lw;
            o2 += m1[u*3 + 2] * lw;
        }
        float gv = gt[v] * INV_SQRT8F;
        x1[v*3 + 0] = o0 * gv;
        x1[v*3 + 1] = o1 * gv;
        x1[v*3 + 2] = o2 * gv;
    }

    float sv0 = 0.f, sv1 = 0.f, sv2 = 0.f;
#pragma unroll
    for (int v = 0; v < 16; v++) {
        float sw = __ldg(&sc2_w[v]);
        sv0 += x1[v*3 + 0] * sw;
        sv1 += x1[v*3 + 1] * sw;
        sv2 += x1[v*3 + 2] * sw;
    }
    g_scv[n*3 + 0] = sv0 * 0.25f;
    g_scv[n*3 + 1] = sv1 * 0.25f;
    g_scv[n*3 + 2] = sv2 * 0.25f;

#pragma unroll
    for (int v = 0; v < 16; v++) {
        float a = 0.f;
#pragma unroll
        for (int u = 0; u < 16; u++) a += x0[u] * __ldg(&lin1b0[u*16 + v]);
        g_a0n[n*16 + v] = a * 0.25f;
    }
#pragma unroll
    for (int v = 0; v < 16; v++) {
        float a0 = 0.f, a1 = 0.f, a2 = 0.f;
#pragma unroll
        for (int u = 0; u < 16; u++) {
            float lw = __ldg(&lin1b1[u*16 + v]);
            a0 += x1[u*3 + 0] * lw;
            a1 += x1[u*3 + 1] * lw;
            a2 += x1[u*3 + 2] * lw;
        }
        g_a1n[n*48 + v*3 + 0] = a0 * 0.25f;
        g_a1n[n*48 + v*3 + 1] = a1 * 0.25f;
        g_a1n[n*48 + v*3 + 2] = a2 * 0.25f;
    }
}

// ---------------------------------------------------------------------------
// Kernel P: per-src contracted tensors for pass 2:
//   P_i  = sum_u W2[i][u]    *a2w[u]   *a0n[u]
//   Qb_i = sum_u W2[i][16+u] *l2b[u]   *a0n[u]
//   R_ic = sum_u W2[i][32+u] *l2b[16+u]*a1n[u][c]
//   S_ic = sum_u W2[i][48+u] *a2w[16+u]*a1n[u][c] / sqrt(3)
// all scaled by K2 = 0.1*inv_nn/sqrt(32)
// layout per src: 100 x {P, Qb, S0,S1,S2, R0,R1,R2}
// ---------------------------------------------------------------------------
__global__ void k_pqrs(const float* __restrict__ fc2_w2,
                       const float* __restrict__ alpha2_w,
                       const float* __restrict__ lin2b)
{
    const int s = blockIdx.x;
    const int i = threadIdx.x;   // blockDim = 128
    __shared__ float a0s[16];
    __shared__ float a1s[48];
    __shared__ float aw[32], lb[32];
    if (i < 16) a0s[i] = g_a0n[s*16 + i];
    if (i < 48) a1s[i] = g_a1n[s*48 + i];
    if (i < 32) { aw[i] = alpha2_w[i]; lb[i] = lin2b[i]; }
    __syncthreads();
    if (i < 100) {
        float P = 0.f, Q = 0.f;
        float S0 = 0.f, S1 = 0.f, S2 = 0.f;
        float R0 = 0.f, R1 = 0.f, R2 = 0.f;
        const float* wr = &fc2_w2[i*64];
#pragma unroll
        for (int u = 0; u < 16; u++) {
            float a0u = a0s[u];
            float a10 = a1s[u*3 + 0], a11 = a1s[u*3 + 1], a12 = a1s[u*3 + 2];
            P += __ldg(&wr[u])      * aw[u]      * a0u;
            Q += __ldg(&wr[16 + u]) * lb[u]      * a0u;
            float rc = __ldg(&wr[32 + u]) * lb[16 + u];
            R0 += rc*a10; R1 += rc*a11; R2 += rc*a12;
            float sc = __ldg(&wr[48 + u]) * aw[16 + u];
            S0 += sc*a10; S1 += sc*a11; S2 += sc*a12;
        }
        const float K2  = 0.1f * INV_NNF * INV_SQRT32F;
        const float K2s = K2 * INV_SQRT3F;
        float4 A = make_float4(P*K2, Q*K2, S0*K2s, S1*K2s);
        float4 B = make_float4(S2*K2s, R0*K2, R1*K2, R2*K2);
        *(float4*)&g_pqrs[s*800 + i*8]     = A;
        *(float4*)&g_pqrs[s*800 + i*8 + 4] = B;
    }
}

// ---------------------------------------------------------------------------
// Kernel D: pass 2. grid = (8 dst-tiles, NSPLIT2 src-splits), 128 threads.
// thread = one dst; all threads of a CTA walk the same src (broadcast loads).
// Per pair only 4 scalar accumulators thanks to the contraction trick.
// ---------------------------------------------------------------------------
__global__ void __launch_bounds__(128)
k_pass2(const float* __restrict__ pos,
        const float* __restrict__ fc2_w1)
{
    __shared__ float  w1t[100*12];
    __shared__ float4 sbuf[200];
    __shared__ float  sposb[4];

    const int tid = threadIdx.x;
    const int d   = blockIdx.x * 128 + tid;
    const int s0  = blockIdx.y * SRC_PER_CTA2;

    for (int idx = tid; idx < 1000; idx += 128) {
        int k = idx / 100, i = idx - k*100;
        w1t[i*12 + k] = fc2_w1[idx];
    }
    const float pdx = pos[d*3+0], pdy = pos[d*3+1], pdz = pos[d*3+2];

    float accA = 0.f, acc0 = 0.f, acc1 = 0.f, acc2 = 0.f;

    for (int s = s0; s < s0 + SRC_PER_CTA2; s++) {
        __syncthreads();
        const float4* src = (const float4*)&g_pqrs[s*800];
        for (int idx = tid; idx < 200; idx += 128) sbuf[idx] = src[idx];
        if (tid < 3) sposb[tid] = pos[s*3 + tid];
        __syncthreads();

        float vx = sposb[0] - pdx;
        float vy = sposb[1] - pdy;
        float vz = sposb[2] - pdz;
        float r2 = fmaxf(vx*vx + vy*vy + vz*vz, 1e-30f);
        float inv_r = rsqrtf(r2);
        float rr = (r2 * inv_r) * INV_STEPF;

        float g[10];
#pragma unroll
        for (int k = 0; k < 10; k++) {
            float t = rr - (float)k;
            g[k] = __expf(-t*t);
        }

        float A = 0.f, B0 = 0.f, B1 = 0.f, B2 = 0.f;
        float C = 0.f, D0 = 0.f, D1 = 0.f, D2 = 0.f;
#pragma unroll 2
        for (int i = 0; i < 100; i++) {
            const float4 wa = *(const float4*)&w1t[i*12];
            const float4 wb = *(const float4*)&w1t[i*12 + 4];
            const float2 wc = *(const float2*)&w1t[i*12 + 8];
            float a = g[0]*wa.x + g[1]*wa.y + g[2]*wa.z + g[3]*wa.w
                    + g[4]*wb.x + g[5]*wb.y + g[6]*wb.z + g[7]*wb.w
                    + g[8]*wc.x + g[9]*wc.y;
            float h = siluf(a);
            const float4 fa = sbuf[i*2];
            const float4 fb = sbuf[i*2 + 1];
            A  += h*fa.x; C  += h*fa.y; B0 += h*fa.z; B1 += h*fa.w;
            B2 += h*fb.x; D0 += h*fb.y; D1 += h*fb.z; D2 += h*fb.w;
        }

        float msk = (s != d) ? 1.f : 0.f;
        float sy = SQRT3F * inv_r;
        float y0 = vx*sy, y1 = vy*sy, y2 = vz*sy;
        accA += msk * (A + y0*B0 + y1*B1 + y2*B2);
        acc0 += msk * (y0*C + D0);
        acc1 += msk * (y1*C + D1);
        acc2 += msk * (y2*C + D2);
    }

    *(float4*)&g_part[(blockIdx.y * NNODES + d) * 4] =
        make_float4(accA, acc0, acc1, acc2);
}

// ---------------------------------------------------------------------------
// Kernel E: reduce partials, final node combine, global sum -> 3 floats
// ---------------------------------------------------------------------------
__global__ void k_final(float* __restrict__ out)
{
    const int d = threadIdx.x;   // 1024 threads, 1 block
    float a2 = 0.f, o0 = 0.f, o1 = 0.f, o2 = 0.f;
#pragma unroll 8
    for (int p = 0; p < NSPLIT2; p++) {
        float4 v = *(const float4*)&g_part[(p * NNODES + d) * 4];
        a2 += v.x; o0 += v.y; o1 += v.z; o2 += v.w;
    }
    float n0 = g_scv[d*3 + 0] + a2 * o0;
    float n1 = g_scv[d*3 + 1] + a2 * o1;
    float n2 = g_scv[d*3 + 2] + a2 * o2;

    __shared__ float red[32*3];
#pragma unroll
    for (int o = 16; o > 0; o >>= 1) {
        n0 += __shfl_xor_sync(0xffffffffu, n0, o);
        n1 += __shfl_xor_sync(0xffffffffu, n1, o);
        n2 += __shfl_xor_sync(0xffffffffu, n2, o);
    }
    int lane = d & 31, wid = d >> 5;
    if (lane == 0) {
        red[wid*3 + 0] = n0;
        red[wid*3 + 1] = n1;
        red[wid*3 + 2] = n2;
    }
    __syncthreads();
    if (d == 0) {
        float s0 = 0.f, s1 = 0.f, s2 = 0.f;
#pragma unroll
        for (int wi = 0; wi < 32; wi++) {
            s0 += red[wi*3 + 0];
            s1 += red[wi*3 + 1];
            s2 += red[wi*3 + 2];
        }
        out[0] = s0 * (1.0f / 32.0f);
        out[1] = s1 * (1.0f / 32.0f);
        out[2] = s2 * (1.0f / 32.0f);
    }
}

// ---------------------------------------------------------------------------
extern "C" void kernel_launch(void* const* d_in, const int* in_sizes, int n_in,
                              void* d_out, int out_size)
{
    // Input order can be either the reference-signature order (weights at
    // index 2..15, edges at 16/17) or the setup_inputs dict order (edges at
    // index 2/3, weights at 4..17). Disambiguate via in_sizes[2]:
    // signature order -> 256 (sc1_w), dict order -> 1047552 (edge_src).
    int wbase = (n_in >= 3 && in_sizes[2] > 100000) ? 4 : 2;

    const float* pos      = (const float*)d_in[0];
    const float* x        = (const float*)d_in[1];
    const float* sc1_w    = (const float*)d_in[wbase + 0];
    const float* lin1a_w  = (const float*)d_in[wbase + 1];
    const float* fc1_w1   = (const float*)d_in[wbase + 2];
    const float* fc1_w2   = (const float*)d_in[wbase + 3];
    const float* lin2a0   = (const float*)d_in[wbase + 4];
    const float* lin2a1   = (const float*)d_in[wbase + 5];
    const float* alpha1_w = (const float*)d_in[wbase + 6];
    const float* sc2_w    = (const float*)d_in[wbase + 7];
    const float* lin1b0   = (const float*)d_in[wbase + 8];
    const float* lin1b1   = (const float*)d_in[wbase + 9];
    const float* fc2_w1   = (const float*)d_in[wbase + 10];
    const float* fc2_w2   = (const float*)d_in[wbase + 11];
    const float* lin2b    = (const float*)d_in[wbase + 12];
    const float* alpha2_w = (const float*)d_in[wbase + 13];

    k_node_pre<<<4, 256>>>(x, lin1a_w, sc1_w);
    k_pass1<<<NNODES, 256>>>(pos, fc1_w1, fc1_w2);
    k_node_mid<<<4, 256>>>(lin2a0, lin2a1, alpha1_w, sc2_w, lin1b0, lin1b1);
    k_pqrs<<<NNODES, 128>>>(fc2_w2, alpha2_w, lin2b);
    dim3 g2(NNODES / 128, NSPLIT2);
    k_pass2<<<g2, 128>>>(pos, fc2_w1);
    k_final<<<1, 1024>>>((float*)d_out);
}

// round 3
// speedup vs baseline: 2.0714x; 2.0714x over previous
#include <cuda_runtime.h>
#include <cuda_fp16.h>
#include <math.h>

#define NNODES 1024
#define TABN   4096
#define FIDX_SCALE (1.8f * 256.0f)   /* r -> table float index (rr*256) */

#define NS1 64
#define SP1 (NNODES/NS1)   /* 16 */
#define NS2 64
#define SP2 (NNODES/NS2)   /* 16 */

#define SQRT3F      1.7320508075688772f
#define INV_SQRT3F  0.5773502691896258f
#define INV_SQRT8F  0.35355339059327373f
#define INV_SQRT32F 0.17677669529663687f
#define INV_NNF     0.031265284f          /* 1/sqrt(1023) */

__device__ float   g_tn [(TABN+1)*80];   // table node values (fp32)
__device__ __half2 g_t1 [TABN*16];       // pass1 table: (v, dv) per func
__device__ __half2 g_t2 [TABN*64];       // pass2 table
__device__ float   g_xl [NNODES*8];      // lin1a(x)/sqrt8 * inv_nn
__device__ float   g_sc [NNODES*32];
__device__ float   g_p1 [NS1*NNODES*32]; // pass1 partials
__device__ float   g_m0 [NNODES*8];
__device__ float   g_m1 [NNODES*24];
__device__ float   g_scv[NNODES*3];
__device__ float   g_coef[NNODES*128];   // per-src pass2 coefficients
__device__ float   g_part[NS2*NNODES*4];

__device__ __forceinline__ float siluf(float a) {
    return __fdividef(a, 1.0f + __expf(-a));
}
__device__ __forceinline__ float sigf(float a) {
    return __fdividef(1.0f, 1.0f + __expf(-a));
}

__device__ __forceinline__ void unpack4(float* w, float4 q, float t) {
    const __half2* h = reinterpret_cast<const __half2*>(&q);
#pragma unroll
    for (int i = 0; i < 4; i++) {
        float2 vd = __half22float2(h[i]);
        w[i] = fmaf(t, vd.y, vd.x);
    }
}

// ---------------------------------------------------------------------------
// Build table node values: for each rr-grid entry, h1/h2 (100 hidden each),
// then 16 pass1 funcs (h1@fc1_w2*0.1) and 64 pass2 funcs (h2@fc2_w2*0.1).
// 32 entries per CTA, staged through smem.
// ---------------------------------------------------------------------------
__global__ void __launch_bounds__(256)
k_table_nodes(const float* __restrict__ fc1_w1, const float* __restrict__ fc1_w2,
              const float* __restrict__ fc2_w1, const float* __restrict__ fc2_w2)
{
    __shared__ float w1a[1000], w1b[1000];
    __shared__ float w2a[1600];
    __shared__ float gs[32*10];
    __shared__ float h1[32*101], h2[32*101];
    const int tid = threadIdx.x;
    const int e0  = blockIdx.x * 32;

    for (int i = tid; i < 1000; i += 256) { w1a[i] = fc1_w1[i]; w1b[i] = fc2_w1[i]; }
    for (int i = tid; i < 1600; i += 256) w2a[i] = fc1_w2[i];
    // FIX (R2 bug): 320 entries > blockDim(256) -> must stride, else rows
    // e=25..31 of every block were uninitialized garbage.
    for (int o = tid; o < 320; o += 256) {
        int e = o / 10, k = o - (o/10)*10;
        float rr = (float)(e0 + e) * (1.0f/256.0f);
        float t = rr - (float)k;
        gs[e*10 + k] = __expf(-t*t);
    }
    __syncthreads();

    for (int o = tid; o < 3200; o += 256) {
        int e = o & 31, i = o >> 5;
        float a1 = 0.f, a2 = 0.f;
#pragma unroll
        for (int k = 0; k < 10; k++) {
            float g = gs[e*10 + k];
            a1 += g * w1a[k*100 + i];
            a2 += g * w1b[k*100 + i];
        }
        h1[e*101 + i] = siluf(a1);
        h2[e*101 + i] = siluf(a2);
    }
    __syncthreads();

    for (int o = tid; o < 2560; o += 256) {
        int e = o & 31, f = o >> 5;
        int eg = e0 + e;
        if (eg > TABN) continue;
        float acc = 0.f;
        if (f < 16) {
#pragma unroll 4
            for (int i = 0; i < 100; i++) acc += h1[e*101 + i] * w2a[i*16 + f];
        } else {
            int f2 = f - 16;
#pragma unroll 4
            for (int i = 0; i < 100; i++) acc += h2[e*101 + i] * __ldg(&fc2_w2[i*64 + f2]);
        }
        g_tn[eg*80 + f] = acc * 0.1f;
    }
}

// ---------------------------------------------------------------------------
__global__ void k_pack()
{
    int idx = blockIdx.x * 256 + threadIdx.x;
    if (idx >= TABN*80) return;
    int e = idx / 80, f = idx - e*80;
    float v  = g_tn[e*80 + f];
    float vn = g_tn[e*80 + 80 + f];
    __half2 p = __floats2half2_rn(v, vn - v);
    if (f < 16) g_t1[e*16 + f] = p;
    else        g_t2[e*64 + (f - 16)] = p;
}

// ---------------------------------------------------------------------------
// Per-node premix: xl = x@lin1a/sqrt8 * inv_nn (folded), sc = x@sc1_w/sqrt8
// ---------------------------------------------------------------------------
__global__ void k_node_pre(const float* __restrict__ x,
                           const float* __restrict__ lin1a_w,
                           const float* __restrict__ sc1_w)
{
    int n = blockIdx.x * blockDim.x + threadIdx.x;
    if (n >= NNODES) return;
    float xr[8];
#pragma unroll
    for (int k = 0; k < 8; k++) xr[k] = x[n*8 + k];
#pragma unroll
    for (int u = 0; u < 8; u++) {
        float a = 0.f;
#pragma unroll
        for (int k = 0; k < 8; k++) a += xr[k] * __ldg(&lin1a_w[k*8 + u]);
        g_xl[n*8 + u] = a * (INV_SQRT8F * INV_NNF);
    }
#pragma unroll
    for (int j = 0; j < 32; j++) {
        float a = 0.f;
#pragma unroll
        for (int k = 0; k < 8; k++) a += xr[k] * __ldg(&sc1_w[k*32 + j]);
        g_sc[n*32 + j] = a * INV_SQRT8F;
    }
}

// ---------------------------------------------------------------------------
// Pass 1: thread = dst, CTA iterates SP1 srcs. Table lookup (16 funcs).
// ---------------------------------------------------------------------------
__global__ void __launch_bounds__(128)
k_pass1(const float* __restrict__ pos)
{
    __shared__ float sxl[SP1*8];
    __shared__ float sps[SP1*4];
    const int tid = threadIdx.x;
    const int d   = blockIdx.x * 128 + tid;
    const int s0  = blockIdx.y * SP1;

    sxl[tid] = g_xl[s0*8 + tid];   // SP1*8 == 128
    if (tid < SP1*4) {
        int j = tid >> 2, c = tid & 3;
        sps[tid] = (c < 3) ? pos[(s0 + j)*3 + c] : 0.f;
    }
    const float pdx = pos[d*3+0], pdy = pos[d*3+1], pdz = pos[d*3+2];

    float acc[32];
#pragma unroll
    for (int q = 0; q < 32; q++) acc[q] = 0.f;
    __syncthreads();

#pragma unroll 1
    for (int j = 0; j < SP1; j++) {
        int s = s0 + j;
        float vx = sps[j*4+0] - pdx;
        float vy = sps[j*4+1] - pdy;
        float vz = sps[j*4+2] - pdz;
        float r2 = fmaxf(vx*vx + vy*vy + vz*vz, 1e-24f);
        float inv_r = rsqrtf(r2);
        float fi = fminf(r2 * inv_r * FIDX_SCALE, 4095.999f);
        int   e  = (int)fi;
        float t  = fi - (float)e;
        const float4* row = (const float4*)&g_t1[e*16];
        float4 q0 = row[0], q1 = row[1], q2 = row[2], q3 = row[3];

        float w[16];
        unpack4(w + 0,  q0, t);
        unpack4(w + 4,  q1, t);
        unpack4(w + 8,  q2, t);
        unpack4(w + 12, q3, t);

        float msk = (s != d) ? 1.f : 0.f;
        float sy = SQRT3F * inv_r;
        float y0 = vx*sy, y1 = vy*sy, y2 = vz*sy;

#pragma unroll
        for (int u = 0; u < 8; u++) {
            float xe = sxl[j*8 + u] * msk;
            acc[u] = fmaf(w[u], xe, acc[u]);
            float tt = w[8+u] * xe;
            acc[8 + u*3 + 0] = fmaf(tt, y0, acc[8 + u*3 + 0]);
            acc[8 + u*3 + 1] = fmaf(tt, y1, acc[8 + u*3 + 1]);
            acc[8 + u*3 + 2] = fmaf(tt, y2, acc[8 + u*3 + 2]);
        }
    }

    float* op = &g_p1[((size_t)blockIdx.y * NNODES + d) * 32];
#pragma unroll
    for (int q = 0; q < 8; q++)
        ((float4*)op)[q] = make_float4(acc[q*4], acc[q*4+1], acc[q*4+2], acc[q*4+3]);
}

// ---------------------------------------------------------------------------
__global__ void k_red1()
{
    int idx = blockIdx.x * 256 + threadIdx.x;   // 32768 total
    int d = idx >> 5, j = idx & 31;
    float s = 0.f;
#pragma unroll 8
    for (int p = 0; p < NS1; p++) s += g_p1[((size_t)p * NNODES + d)*32 + j];
    if (j < 8) g_m0[d*8 + j] = s;
    else       g_m1[d*24 + (j - 8)] = s;
}

// ---------------------------------------------------------------------------
// Node middle stage -> scv + per-src pass2 coefficient vectors (128 floats)
// ---------------------------------------------------------------------------
__global__ void k_node_mid(const float* __restrict__ lin2a0,
                           const float* __restrict__ lin2a1,
                           const float* __restrict__ alpha1_w,
                           const float* __restrict__ sc2_w,
                           const float* __restrict__ lin1b0,
                           const float* __restrict__ lin1b1,
                           const float* __restrict__ alpha2_w,
                           const float* __restrict__ lin2b)
{
    int n = blockIdx.x * blockDim.x + threadIdx.x;
    if (n >= NNODES) return;

    float m0[8], m1[24];
#pragma unroll
    for (int u = 0; u < 8; u++)  m0[u] = g_m0[n*8 + u];
#pragma unroll
    for (int j = 0; j < 24; j++) m1[j] = g_m1[n*24 + j];

    float alpha = 0.f;
#pragma unroll
    for (int u = 0; u < 8; u++) alpha += m0[u] * __ldg(&alpha1_w[u]);
    alpha *= INV_SQRT8F;

    float x0[16], gt[16];
#pragma unroll
    for (int j = 0; j < 32; j++) {
        float o = 0.f;
#pragma unroll
        for (int u = 0; u < 8; u++) o += m0[u] * __ldg(&lin2a0[u*32 + j]);
        float sv = g_sc[n*32 + j] + alpha * (o * INV_SQRT8F);
        if (j < 16) x0[j] = siluf(sv);
        else        gt[j - 16] = sigf(sv);
    }

    float x1[48];
#pragma unroll
    for (int v = 0; v < 16; v++) {
        float o0 = 0.f, o1 = 0.f, o2 = 0.f;
#pragma unroll
        for (int u = 0; u < 8; u++) {
            float lw = __ldg(&lin2a1[u*16 + v]);
            o0 += m1[u*3 + 0] * lw;
            o1 += m1[u*3 + 1] * lw;
            o2 += m1[u*3 + 2] * lw;
        }
        float gv = gt[v] * INV_SQRT8F;
        x1[v*3 + 0] = o0 * gv;
        x1[v*3 + 1] = o1 * gv;
        x1[v*3 + 2] = o2 * gv;
    }

    float sv0 = 0.f, sv1 = 0.f, sv2 = 0.f;
#pragma unroll
    for (int v = 0; v < 16; v++) {
        float sw = __ldg(&sc2_w[v]);
        sv0 += x1[v*3 + 0] * sw;
        sv1 += x1[v*3 + 1] * sw;
        sv2 += x1[v*3 + 2] * sw;
    }
    g_scv[n*3 + 0] = sv0 * 0.25f;
    g_scv[n*3 + 1] = sv1 * 0.25f;
    g_scv[n*3 + 2] = sv2 * 0.25f;

    // a0n / a1n (with 1/sqrt16 = 0.25 folded)
    float a0v[16], a1v[48];
#pragma unroll
    for (int v = 0; v < 16; v++) {
        float a = 0.f;
#pragma unroll
        for (int u = 0; u < 16; u++) a += x0[u] * __ldg(&lin1b0[u*16 + v]);
        a0v[v] = a * 0.25f;
    }
#pragma unroll
    for (int v = 0; v < 16; v++) {
        float a0 = 0.f, a1 = 0.f, a2 = 0.f;
#pragma unroll
        for (int u = 0; u < 16; u++) {
            float lw = __ldg(&lin1b1[u*16 + v]);
            a0 += x1[u*3 + 0] * lw;
            a1 += x1[u*3 + 1] * lw;
            a2 += x1[u*3 + 2] * lw;
        }
        a1v[v*3 + 0] = a0 * 0.25f;
        a1v[v*3 + 1] = a1 * 0.25f;
        a1v[v*3 + 2] = a2 * 0.25f;
    }

    // pass2 coefficients: [cA(16) | cQ(16) | cD(48) | cS(48)], scale folded
    const float Kc = INV_NNF * INV_SQRT32F;
    float* cf = &g_coef[n*128];
#pragma unroll
    for (int u = 0; u < 16; u++) {
        cf[u]      = __ldg(&alpha2_w[u]) * a0v[u] * Kc;
        cf[16 + u] = __ldg(&lin2b[u])    * a0v[u] * Kc;
        float lw = __ldg(&lin2b[16 + u])    * Kc;
        float aw = __ldg(&alpha2_w[16 + u]) * Kc * INV_SQRT3F;
#pragma unroll
        for (int c = 0; c < 3; c++) {
            cf[32 + u*3 + c] = lw * a1v[u*3 + c];
            cf[80 + u*3 + c] = aw * a1v[u*3 + c];
        }
    }
}

// ---------------------------------------------------------------------------
// Pass 2: thread = dst, CTA iterates SP2 srcs. Table lookup (64 funcs) +
// contraction with per-src coefficients from smem.
// ---------------------------------------------------------------------------
__global__ void __launch_bounds__(128)
k_pass2(const float* __restrict__ pos)
{
    __shared__ float scoef[SP2*128];
    __shared__ float sps[SP2*4];
    const int tid = threadIdx.x;
    const int d   = blockIdx.x * 128 + tid;
    const int s0  = blockIdx.y * SP2;

    for (int q = tid; q < SP2*32; q += 128)
        ((float4*)scoef)[q] = ((const float4*)&g_coef[s0*128])[q];
    if (tid < SP2*4) {
        int j = tid >> 2, c = tid & 3;
        sps[tid] = (c < 3) ? pos[(s0 + j)*3 + c] : 0.f;
    }
    const float pdx = pos[d*3+0], pdy = pos[d*3+1], pdz = pos[d*3+2];

    float accA = 0.f, ac0 = 0.f, ac1 = 0.f, ac2 = 0.f;
    __syncthreads();

#pragma unroll 1
    for (int j = 0; j < SP2; j++) {
        int s = s0 + j;
        float vx = sps[j*4+0] - pdx;
        float vy = sps[j*4+1] - pdy;
        float vz = sps[j*4+2] - pdz;
        float r2 = fmaxf(vx*vx + vy*vy + vz*vz, 1e-24f);
        float inv_r = rsqrtf(r2);
        float fi = fminf(r2 * inv_r * FIDX_SCALE, 4095.999f);
        int   e  = (int)fi;
        float t  = fi - (float)e;
        const float4* row = (const float4*)&g_t2[e*64];
        const float*  cf  = &scoef[j*128];

        float A = 0.f, Q = 0.f;
        float D0 = 0.f, D1 = 0.f, D2 = 0.f;
        float S0 = 0.f, S1 = 0.f, S2 = 0.f;

#pragma unroll
        for (int q = 0; q < 4; q++) {
            float w[4]; unpack4(w, row[q], t);
#pragma unroll
            for (int ww = 0; ww < 4; ww++) A = fmaf(w[ww], cf[q*4 + ww], A);
        }
#pragma unroll
        for (int q = 0; q < 4; q++) {
            float w[4]; unpack4(w, row[4 + q], t);
#pragma unroll
            for (int ww = 0; ww < 4; ww++) Q = fmaf(w[ww], cf[16 + q*4 + ww], Q);
        }
#pragma unroll
        for (int q = 0; q < 4; q++) {
            float w[4]; unpack4(w, row[8 + q], t);
#pragma unroll
            for (int ww = 0; ww < 4; ww++) {
                int u = q*4 + ww;
                D0 = fmaf(w[ww], cf[32 + u*3 + 0], D0);
                D1 = fmaf(w[ww], cf[32 + u*3 + 1], D1);
                D2 = fmaf(w[ww], cf[32 + u*3 + 2], D2);
            }
        }
#pragma unroll
        for (int q = 0; q < 4; q++) {
            float w[4]; unpack4(w, row[12 + q], t);
#pragma unroll
            for (int ww = 0; ww < 4; ww++) {
                int u = q*4 + ww;
                S0 = fmaf(w[ww], cf[80 + u*3 + 0], S0);
                S1 = fmaf(w[ww], cf[80 + u*3 + 1], S1);
                S2 = fmaf(w[ww], cf[80 + u*3 + 2], S2);
            }
        }

        float msk = (s != d) ? 1.f : 0.f;
        float sy = SQRT3F * inv_r;
        float y0 = vx*sy, y1 = vy*sy, y2 = vz*sy;
        accA += msk * (A + y0*S0 + y1*S1 + y2*S2);
        ac0  += msk * fmaf(y0, Q, D0);
        ac1  += msk * fmaf(y1, Q, D1);
        ac2  += msk * fmaf(y2, Q, D2);
    }

    *(float4*)&g_part[((size_t)blockIdx.y * NNODES + d) * 4] =
        make_float4(accA, ac0, ac1, ac2);
}

// ---------------------------------------------------------------------------
__global__ void k_final(float* __restrict__ out)
{
    const int d = threadIdx.x;   // 1024 threads, 1 block
    float a2 = 0.f, o0 = 0.f, o1 = 0.f, o2 = 0.f;
#pragma unroll 8
    for (int p = 0; p < NS2; p++) {
        float4 v = *(const float4*)&g_part[((size_t)p * NNODES + d) * 4];
        a2 += v.x; o0 += v.y; o1 += v.z; o2 += v.w;
    }
    float n0 = g_scv[d*3 + 0] + a2 * o0;
    float n1 = g_scv[d*3 + 1] + a2 * o1;
    float n2 = g_scv[d*3 + 2] + a2 * o2;

    __shared__ float red[32*3];
#pragma unroll
    for (int o = 16; o > 0; o >>= 1) {
        n0 += __shfl_xor_sync(0xffffffffu, n0, o);
        n1 += __shfl_xor_sync(0xffffffffu, n1, o);
        n2 += __shfl_xor_sync(0xffffffffu, n2, o);
    }
    int lane = d & 31, wid = d >> 5;
    if (lane == 0) {
        red[wid*3 + 0] = n0;
        red[wid*3 + 1] = n1;
        red[wid*3 + 2] = n2;
    }
    __syncthreads();
    if (d == 0) {
        float s0 = 0.f, s1 = 0.f, s2 = 0.f;
#pragma unroll
        for (int wi = 0; wi < 32; wi++) {
            s0 += red[wi*3 + 0];
            s1 += red[wi*3 + 1];
            s2 += red[wi*3 + 2];
        }
        out[0] = s0 * (1.0f / 32.0f);
        out[1] = s1 * (1.0f / 32.0f);
        out[2] = s2 * (1.0f / 32.0f);
    }
}

// ---------------------------------------------------------------------------
extern "C" void kernel_launch(void* const* d_in, const int* in_sizes, int n_in,
                              void* d_out, int out_size)
{
    int wbase = (n_in >= 3 && in_sizes[2] > 100000) ? 4 : 2;

    const float* pos      = (const float*)d_in[0];
    const float* x        = (const float*)d_in[1];
    const float* sc1_w    = (const float*)d_in[wbase + 0];
    const float* lin1a_w  = (const float*)d_in[wbase + 1];
    const float* fc1_w1   = (const float*)d_in[wbase + 2];
    const float* fc1_w2   = (const float*)d_in[wbase + 3];
    const float* lin2a0   = (const float*)d_in[wbase + 4];
    const float* lin2a1   = (const float*)d_in[wbase + 5];
    const float* alpha1_w = (const float*)d_in[wbase + 6];
    const float* sc2_w    = (const float*)d_in[wbase + 7];
    const float* lin1b0   = (const float*)d_in[wbase + 8];
    const float* lin1b1   = (const float*)d_in[wbase + 9];
    const float* fc2_w1   = (const float*)d_in[wbase + 10];
    const float* fc2_w2   = (const float*)d_in[wbase + 11];
    const float* lin2b    = (const float*)d_in[wbase + 12];
    const float* alpha2_w = (const float*)d_in[wbase + 13];

    k_table_nodes<<<(TABN/32) + 1, 256>>>(fc1_w1, fc1_w2, fc2_w1, fc2_w2);
    k_pack<<<(TABN*80 + 255)/256, 256>>>();
    k_node_pre<<<4, 256>>>(x, lin1a_w, sc1_w);
    k_pass1<<<dim3(NNODES/128, NS1), 128>>>(pos);
    k_red1<<<128, 256>>>();
    k_node_mid<<<4, 256>>>(lin2a0, lin2a1, alpha1_w, sc2_w,
                           lin1b0, lin1b1, alpha2_w, lin2b);
    k_pass2<<<dim3(NNODES/128, NS2), 128>>>(pos);
    k_final<<<1, 1024>>>((float*)d_out);
}

// round 4
// speedup vs baseline: 2.6994x; 1.3031x over previous
#include <cuda_runtime.h>
#include <cuda_fp16.h>
#include <math.h>

#define NNODES 1024
#define TABN   1024              /* usable rows 0..1023 */
#define FIDX_SCALE 115.2f        /* r * 1.8 (->rr) * 64 (rows per rr unit) */
#define FIDX_MAX   1022.999f     /* e <= 1022, e+1 <= 1023 */

#define NS1 74                   /* pass1 src splits: 4*74 = 296 CTAs */
#define SPMAX1 14
#define NS2 37                   /* pass2 src splits: 4*37 = 148 CTAs */
#define SPMAX2 28

#define SQRT3F      1.7320508075688772f
#define INV_SQRT3F  0.5773502691896258f
#define INV_SQRT8F  0.35355339059327373f
#define INV_SQRT32F 0.17677669529663687f
#define INV_NNF     0.031265284f          /* 1/sqrt(1023) */

/* fp16 value-only tables (16B aligned for float4 bulk copies) */
__device__ __align__(16) __half g_t1h[TABN*16];
__device__ __align__(16) __half g_t2h[TABN*64];
__device__ float g_xl [NNODES*8];
__device__ float g_sc [NNODES*32];
__device__ float g_p1 [NS1*NNODES*32];
__device__ float g_m0 [NNODES*8];
__device__ float g_m1 [NNODES*24];
__device__ float g_scv[NNODES*3];
__device__ float g_coef[NNODES*128];
__device__ float g_part[NS2*NNODES*4];

/* dynamic smem layouts */
#define SM1_TAB   (TABN*48)                      /* 49152 */
#define SM1_XL    (SM1_TAB)
#define SM1_PS    (SM1_TAB + SPMAX1*8*4)
#define SMEM1     (SM1_TAB + SPMAX1*8*4 + SPMAX1*4*4)

#define SM2_TAB   (TABN*144)                     /* 147456 */
#define SM2_CF    (SM2_TAB)
#define SM2_PS    (SM2_TAB + SPMAX2*128*4)
#define SMEM2     (SM2_TAB + SPMAX2*128*4 + SPMAX2*4*4)

__device__ __forceinline__ float siluf(float a) {
    return __fdividef(a, 1.0f + __expf(-a));
}
__device__ __forceinline__ float sigf(float a) {
    return __fdividef(1.0f, 1.0f + __expf(-a));
}

// ---------------------------------------------------------------------------
// k_prep: blocks 0..31 build the fp16 tables (32 rr-entries each);
//         blocks 32..35 do the per-node premix (node_pre).
// ---------------------------------------------------------------------------
__global__ void __launch_bounds__(256)
k_prep(const float* __restrict__ fc1_w1, const float* __restrict__ fc1_w2,
       const float* __restrict__ fc2_w1, const float* __restrict__ fc2_w2,
       const float* __restrict__ x,      const float* __restrict__ lin1a_w,
       const float* __restrict__ sc1_w)
{
    const int tid = threadIdx.x;
    const int bid = blockIdx.x;

    if (bid < 32) {
        __shared__ float w1a[1000], w1b[1000];
        __shared__ float w2a[1600];
        __shared__ float gs[32*10];
        __shared__ float h1[32*101], h2[32*101];
        const int e0 = bid * 32;

        for (int i = tid; i < 1000; i += 256) { w1a[i] = fc1_w1[i]; w1b[i] = fc2_w1[i]; }
        for (int i = tid; i < 1600; i += 256) w2a[i] = fc1_w2[i];
        for (int o = tid; o < 320; o += 256) {           /* strided: 320 > 256 */
            int e = o / 10, k = o - (o/10)*10;
            float rr = (float)(e0 + e) * (1.0f/64.0f);
            float t = rr - (float)k;
            gs[e*10 + k] = __expf(-t*t);
        }
        __syncthreads();

        for (int o = tid; o < 3200; o += 256) {
            int e = o & 31, i = o >> 5;
            float a1 = 0.f, a2 = 0.f;
#pragma unroll
            for (int k = 0; k < 10; k++) {
                float g = gs[e*10 + k];
                a1 += g * w1a[k*100 + i];
                a2 += g * w1b[k*100 + i];
            }
            h1[e*101 + i] = siluf(a1);
            h2[e*101 + i] = siluf(a2);
        }
        __syncthreads();

        for (int o = tid; o < 2560; o += 256) {
            int e = o & 31, f = o >> 5;
            int eg = e0 + e;
            float acc = 0.f;
            if (f < 16) {
#pragma unroll 4
                for (int i = 0; i < 100; i++) acc += h1[e*101 + i] * w2a[i*16 + f];
                g_t1h[eg*16 + f] = __float2half(acc * 0.1f);
            } else {
                int f2 = f - 16;
#pragma unroll 4
                for (int i = 0; i < 100; i++) acc += h2[e*101 + i] * __ldg(&fc2_w2[i*64 + f2]);
                g_t2h[eg*64 + f2] = __float2half(acc * 0.1f);
            }
        }
    } else {
        int n = (bid - 32) * 256 + tid;
        if (n >= NNODES) return;
        float xr[8];
#pragma unroll
        for (int k = 0; k < 8; k++) xr[k] = x[n*8 + k];
#pragma unroll
        for (int u = 0; u < 8; u++) {
            float a = 0.f;
#pragma unroll
            for (int k = 0; k < 8; k++) a += xr[k] * __ldg(&lin1a_w[k*8 + u]);
            g_xl[n*8 + u] = a * (INV_SQRT8F * INV_NNF);
        }
#pragma unroll
        for (int j = 0; j < 32; j++) {
            float a = 0.f;
#pragma unroll
            for (int k = 0; k < 8; k++) a += xr[k] * __ldg(&sc1_w[k*32 + j]);
            g_sc[n*32 + j] = a * INV_SQRT8F;
        }
    }
}

// ---------------------------------------------------------------------------
// Pass 1: thread = dst (256/CTA), CTA iterates its src window.
// Table (16 funcs, fp16 values, 48B-padded rows) lives in smem.
// ---------------------------------------------------------------------------
__global__ void __launch_bounds__(256)
k_pass1(const float* __restrict__ pos)
{
    extern __shared__ char sm[];
    float* sxl = (float*)(sm + SM1_XL);
    float* sps = (float*)(sm + SM1_PS);

    const int tid = threadIdx.x;
    const int d   = blockIdx.x * 256 + tid;
    const int s0  = (blockIdx.y * NNODES) / NS1;
    const int s1  = ((blockIdx.y + 1) * NNODES) / NS1;
    const int cnt = s1 - s0;

    {   /* stage table: global rows are 2 float4, smem rows are 3 (padded) */
        const float4* gt = (const float4*)g_t1h;
        float4* st = (float4*)sm;
        for (int i = tid; i < TABN*2; i += 256) {
            int row = i >> 1, u = i & 1;
            st[row*3 + u] = gt[i];
        }
    }
    for (int i = tid; i < cnt*8; i += 256) sxl[i] = g_xl[s0*8 + i];
    for (int i = tid; i < cnt*4; i += 256) {
        int j = i >> 2, c = i & 3;
        sps[i] = (c < 3) ? pos[(s0 + j)*3 + c] : 0.f;
    }
    const float pdx = pos[d*3+0], pdy = pos[d*3+1], pdz = pos[d*3+2];

    float acc[32];
#pragma unroll
    for (int q = 0; q < 32; q++) acc[q] = 0.f;
    __syncthreads();

#pragma unroll 1
    for (int j = 0; j < cnt; j++) {
        int s = s0 + j;
        float vx = sps[j*4+0] - pdx;
        float vy = sps[j*4+1] - pdy;
        float vz = sps[j*4+2] - pdz;
        float r2 = fmaxf(vx*vx + vy*vy + vz*vz, 1e-24f);
        float inv_r = rsqrtf(r2);
        float fi = fminf(r2 * inv_r * FIDX_SCALE, FIDX_MAX);
        int   e  = (int)fi;
        float t  = fi - (float)e;
        __half2 th = __floats2half2_rn(t, t);

        const float4* Te = (const float4*)(sm + e*48);
        const float4* Tf = (const float4*)(sm + e*48 + 48);
        float w[16];
#pragma unroll
        for (int q = 0; q < 2; q++) {
            float4 va = Te[q], vb = Tf[q];
            const __half2* ha = (const __half2*)&va;
            const __half2* hb = (const __half2*)&vb;
#pragma unroll
            for (int p = 0; p < 4; p++) {
                __half2 w2 = __hfma2(th, __hsub2(hb[p], ha[p]), ha[p]);
                float2 wf = __half22float2(w2);
                w[q*8 + p*2]     = wf.x;
                w[q*8 + p*2 + 1] = wf.y;
            }
        }

        float msk = (s != d) ? 1.f : 0.f;
        float sy = SQRT3F * inv_r;
        float y0 = vx*sy, y1 = vy*sy, y2 = vz*sy;

#pragma unroll
        for (int u = 0; u < 8; u++) {
            float xe = sxl[j*8 + u] * msk;
            acc[u] = fmaf(w[u], xe, acc[u]);
            float tt = w[8+u] * xe;
            acc[8 + u*3 + 0] = fmaf(tt, y0, acc[8 + u*3 + 0]);
            acc[8 + u*3 + 1] = fmaf(tt, y1, acc[8 + u*3 + 1]);
            acc[8 + u*3 + 2] = fmaf(tt, y2, acc[8 + u*3 + 2]);
        }
    }

    float* op = &g_p1[((size_t)blockIdx.y * NNODES + d) * 32];
#pragma unroll
    for (int q = 0; q < 8; q++)
        ((float4*)op)[q] = make_float4(acc[q*4], acc[q*4+1], acc[q*4+2], acc[q*4+3]);
}

// ---------------------------------------------------------------------------
__global__ void k_red1()
{
    int idx = blockIdx.x * 256 + threadIdx.x;   // 32768 total
    int d = idx >> 5, j = idx & 31;
    float s = 0.f;
#pragma unroll 2
    for (int p = 0; p < NS1; p++) s += g_p1[((size_t)p * NNODES + d)*32 + j];
    if (j < 8) g_m0[d*8 + j] = s;
    else       g_m1[d*24 + (j - 8)] = s;
}

// ---------------------------------------------------------------------------
// Node middle stage -> scv + per-src pass2 coefficient vectors (128 floats)
// ---------------------------------------------------------------------------
__global__ void k_node_mid(const float* __restrict__ lin2a0,
                           const float* __restrict__ lin2a1,
                           const float* __restrict__ alpha1_w,
                           const float* __restrict__ sc2_w,
                           const float* __restrict__ lin1b0,
                           const float* __restrict__ lin1b1,
                           const float* __restrict__ alpha2_w,
                           const float* __restrict__ lin2b)
{
    int n = blockIdx.x * blockDim.x + threadIdx.x;
    if (n >= NNODES) return;

    float m0[8], m1[24];
#pragma unroll
    for (int u = 0; u < 8; u++)  m0[u] = g_m0[n*8 + u];
#pragma unroll
    for (int j = 0; j < 24; j++) m1[j] = g_m1[n*24 + j];

    float alpha = 0.f;
#pragma unroll
    for (int u = 0; u < 8; u++) alpha += m0[u] * __ldg(&alpha1_w[u]);
    alpha *= INV_SQRT8F;

    float x0[16], gt[16];
#pragma unroll
    for (int j = 0; j < 32; j++) {
        float o = 0.f;
#pragma unroll
        for (int u = 0; u < 8; u++) o += m0[u] * __ldg(&lin2a0[u*32 + j]);
        float sv = g_sc[n*32 + j] + alpha * (o * INV_SQRT8F);
        if (j < 16) x0[j] = siluf(sv);
        else        gt[j - 16] = sigf(sv);
    }

    float x1[48];
#pragma unroll
    for (int v = 0; v < 16; v++) {
        float o0 = 0.f, o1 = 0.f, o2 = 0.f;
#pragma unroll
        for (int u = 0; u < 8; u++) {
            float lw = __ldg(&lin2a1[u*16 + v]);
            o0 += m1[u*3 + 0] * lw;
            o1 += m1[u*3 + 1] * lw;
            o2 += m1[u*3 + 2] * lw;
        }
        float gv = gt[v] * INV_SQRT8F;
        x1[v*3 + 0] = o0 * gv;
        x1[v*3 + 1] = o1 * gv;
        x1[v*3 + 2] = o2 * gv;
    }

    float sv0 = 0.f, sv1 = 0.f, sv2 = 0.f;
#pragma unroll
    for (int v = 0; v < 16; v++) {
        float sw = __ldg(&sc2_w[v]);
        sv0 += x1[v*3 + 0] * sw;
        sv1 += x1[v*3 + 1] * sw;
        sv2 += x1[v*3 + 2] * sw;
    }
    g_scv[n*3 + 0] = sv0 * 0.25f;
    g_scv[n*3 + 1] = sv1 * 0.25f;
    g_scv[n*3 + 2] = sv2 * 0.25f;

    float a0v[16], a1v[48];
#pragma unroll
    for (int v = 0; v < 16; v++) {
        float a = 0.f;
#pragma unroll
        for (int u = 0; u < 16; u++) a += x0[u] * __ldg(&lin1b0[u*16 + v]);
        a0v[v] = a * 0.25f;
    }
#pragma unroll
    for (int v = 0; v < 16; v++) {
        float a0 = 0.f, a1 = 0.f, a2 = 0.f;
#pragma unroll
        for (int u = 0; u < 16; u++) {
            float lw = __ldg(&lin1b1[u*16 + v]);
            a0 += x1[u*3 + 0] * lw;
            a1 += x1[u*3 + 1] * lw;
            a2 += x1[u*3 + 2] * lw;
        }
        a1v[v*3 + 0] = a0 * 0.25f;
        a1v[v*3 + 1] = a1 * 0.25f;
        a1v[v*3 + 2] = a2 * 0.25f;
    }

    const float Kc = INV_NNF * INV_SQRT32F;
    float* cf = &g_coef[n*128];
#pragma unroll
    for (int u = 0; u < 16; u++) {
        cf[u]      = __ldg(&alpha2_w[u]) * a0v[u] * Kc;
        cf[16 + u] = __ldg(&lin2b[u])    * a0v[u] * Kc;
        float lw = __ldg(&lin2b[16 + u])    * Kc;
        float aw = __ldg(&alpha2_w[16 + u]) * Kc * INV_SQRT3F;
#pragma unroll
        for (int c = 0; c < 3; c++) {
            cf[32 + u*3 + c] = lw * a1v[u*3 + c];
            cf[80 + u*3 + c] = aw * a1v[u*3 + c];
        }
    }
}

// ---------------------------------------------------------------------------
// Pass 2: thread = dst (256/CTA), CTA iterates its src window.
// Table (64 funcs, fp16 values, 144B-padded rows) in smem + per-src coefs.
// ---------------------------------------------------------------------------
__global__ void __launch_bounds__(256)
k_pass2(const float* __restrict__ pos)
{
    extern __shared__ char sm[];
    float* scf = (float*)(sm + SM2_CF);
    float* sps = (float*)(sm + SM2_PS);

    const int tid = threadIdx.x;
    const int d   = blockIdx.x * 256 + tid;
    const int s0  = (blockIdx.y * NNODES) / NS2;
    const int s1  = ((blockIdx.y + 1) * NNODES) / NS2;
    const int cnt = s1 - s0;

    {   /* stage table: global rows 8 float4 -> smem rows 9 (padded) */
        const float4* gt = (const float4*)g_t2h;
        float4* st = (float4*)sm;
        for (int i = tid; i < TABN*8; i += 256) {
            int row = i >> 3, u = i & 7;
            st[row*9 + u] = gt[i];
        }
    }
    {
        const float4* cg = (const float4*)&g_coef[s0*128];
        float4* cs = (float4*)scf;
        for (int i = tid; i < cnt*32; i += 256) cs[i] = cg[i];
    }
    for (int i = tid; i < cnt*4; i += 256) {
        int j = i >> 2, c = i & 3;
        sps[i] = (c < 3) ? pos[(s0 + j)*3 + c] : 0.f;
    }
    const float pdx = pos[d*3+0], pdy = pos[d*3+1], pdz = pos[d*3+2];

    float accA = 0.f, ac0 = 0.f, ac1 = 0.f, ac2 = 0.f;
    __syncthreads();

#pragma unroll 1
    for (int j = 0; j < cnt; j++) {
        int s = s0 + j;
        float vx = sps[j*4+0] - pdx;
        float vy = sps[j*4+1] - pdy;
        float vz = sps[j*4+2] - pdz;
        float r2 = fmaxf(vx*vx + vy*vy + vz*vz, 1e-24f);
        float inv_r = rsqrtf(r2);
        float fi = fminf(r2 * inv_r * FIDX_SCALE, FIDX_MAX);
        int   e  = (int)fi;
        float t  = fi - (float)e;
        __half2 th = __floats2half2_rn(t, t);

        const float4* Te = (const float4*)(sm + e*144);
        const float4* Tf = Te + 9;
        const float*  cf = &scf[j*128];

        float A = 0.f, Q = 0.f;
        float D0 = 0.f, D1 = 0.f, D2 = 0.f;
        float S0 = 0.f, S1 = 0.f, S2 = 0.f;

#pragma unroll
        for (int q = 0; q < 8; q++) {
            float4 va = Te[q], vb = Tf[q];
            const __half2* ha = (const __half2*)&va;
            const __half2* hb = (const __half2*)&vb;
#pragma unroll
            for (int p = 0; p < 4; p++) {
                int f = q*8 + p*2;
                __half2 w2 = __hfma2(th, __hsub2(hb[p], ha[p]), ha[p]);
                float2 wf = __half22float2(w2);
                if (f < 16) {
                    A = fmaf(wf.x, cf[f], A);
                    A = fmaf(wf.y, cf[f+1], A);
                } else if (f < 32) {
                    Q = fmaf(wf.x, cf[f], Q);
                    Q = fmaf(wf.y, cf[f+1], Q);
                } else if (f < 48) {
                    int u = f - 32;
                    D0 = fmaf(wf.x, cf[32+u*3+0], D0); D0 = fmaf(wf.y, cf[32+u*3+3], D0);
                    D1 = fmaf(wf.x, cf[32+u*3+1], D1); D1 = fmaf(wf.y, cf[32+u*3+4], D1);
                    D2 = fmaf(wf.x, cf[32+u*3+2], D2); D2 = fmaf(wf.y, cf[32+u*3+5], D2);
                } else {
                    int u = f - 48;
                    S0 = fmaf(wf.x, cf[80+u*3+0], S0); S0 = fmaf(wf.y, cf[80+u*3+3], S0);
                    S1 = fmaf(wf.x, cf[80+u*3+1], S1); S1 = fmaf(wf.y, cf[80+u*3+4], S1);
                    S2 = fmaf(wf.x, cf[80+u*3+2], S2); S2 = fmaf(wf.y, cf[80+u*3+5], S2);
                }
            }
        }

        float msk = (s != d) ? 1.f : 0.f;
        float sy = SQRT3F * inv_r;
        float y0 = vx*sy, y1 = vy*sy, y2 = vz*sy;
        accA += msk * (A + y0*S0 + y1*S1 + y2*S2);
        ac0  += msk * fmaf(y0, Q, D0);
        ac1  += msk * fmaf(y1, Q, D1);
        ac2  += msk * fmaf(y2, Q, D2);
    }

    *(float4*)&g_part[((size_t)blockIdx.y * NNODES + d) * 4] =
        make_float4(accA, ac0, ac1, ac2);
}

// ---------------------------------------------------------------------------
__global__ void k_final(float* __restrict__ out)
{
    const int d = threadIdx.x;   // 1024 threads, 1 block
    float a2 = 0.f, o0 = 0.f, o1 = 0.f, o2 = 0.f;
#pragma unroll 1
    for (int p = 0; p < NS2; p++) {
        float4 v = *(const float4*)&g_part[((size_t)p * NNODES + d) * 4];
        a2 += v.x; o0 += v.y; o1 += v.z; o2 += v.w;
    }
    float n0 = g_scv[d*3 + 0] + a2 * o0;
    float n1 = g_scv[d*3 + 1] + a2 * o1;
    float n2 = g_scv[d*3 + 2] + a2 * o2;

    __shared__ float red[32*3];
#pragma unroll
    for (int o = 16; o > 0; o >>= 1) {
        n0 += __shfl_xor_sync(0xffffffffu, n0, o);
        n1 += __shfl_xor_sync(0xffffffffu, n1, o);
        n2 += __shfl_xor_sync(0xffffffffu, n2, o);
    }
    int lane = d & 31, wid = d >> 5;
    if (lane == 0) {
        red[wid*3 + 0] = n0;
        red[wid*3 + 1] = n1;
        red[wid*3 + 2] = n2;
    }
    __syncthreads();
    if (d == 0) {
        float s0 = 0.f, s1 = 0.f, s2 = 0.f;
#pragma unroll
        for (int wi = 0; wi < 32; wi++) {
            s0 += red[wi*3 + 0];
            s1 += red[wi*3 + 1];
            s2 += red[wi*3 + 2];
        }
        out[0] = s0 * (1.0f / 32.0f);
        out[1] = s1 * (1.0f / 32.0f);
        out[2] = s2 * (1.0f / 32.0f);
    }
}

// ---------------------------------------------------------------------------
extern "C" void kernel_launch(void* const* d_in, const int* in_sizes, int n_in,
                              void* d_out, int out_size)
{
    int wbase = (n_in >= 3 && in_sizes[2] > 100000) ? 4 : 2;

    const float* pos      = (const float*)d_in[0];
    const float* x        = (const float*)d_in[1];
    const float* sc1_w    = (const float*)d_in[wbase + 0];
    const float* lin1a_w  = (const float*)d_in[wbase + 1];
    const float* fc1_w1   = (const float*)d_in[wbase + 2];
    const float* fc1_w2   = (const float*)d_in[wbase + 3];
    const float* lin2a0   = (const float*)d_in[wbase + 4];
    const float* lin2a1   = (const float*)d_in[wbase + 5];
    const float* alpha1_w = (const float*)d_in[wbase + 6];
    const float* sc2_w    = (const float*)d_in[wbase + 7];
    const float* lin1b0   = (const float*)d_in[wbase + 8];
    const float* lin1b1   = (const float*)d_in[wbase + 9];
    const float* fc2_w1   = (const float*)d_in[wbase + 10];
    const float* fc2_w2   = (const float*)d_in[wbase + 11];
    const float* lin2b    = (const float*)d_in[wbase + 12];
    const float* alpha2_w = (const float*)d_in[wbase + 13];

    cudaFuncSetAttribute(k_pass1, cudaFuncAttributeMaxDynamicSharedMemorySize, SMEM1);
    cudaFuncSetAttribute(k_pass2, cudaFuncAttributeMaxDynamicSharedMemorySize, SMEM2);

    k_prep<<<36, 256>>>(fc1_w1, fc1_w2, fc2_w1, fc2_w2, x, lin1a_w, sc1_w);
    k_pass1<<<dim3(4, NS1), 256, SMEM1>>>(pos);
    k_red1<<<128, 256>>>();
    k_node_mid<<<4, 256>>>(lin2a0, lin2a1, alpha1_w, sc2_w,
                           lin1b0, lin1b1, alpha2_w, lin2b);
    k_pass2<<<dim3(4, NS2), 256, SMEM2>>>(pos);
    k_final<<<1, 1024>>>((float*)d_out);
}

// round 5
// speedup vs baseline: 3.2742x; 1.2130x over previous
#include <cuda_runtime.h>
#include <cuda_fp16.h>
#include <math.h>

#define NNODES 1024
#define TABN   1024              /* usable rows 0..1023 */
#define FIDX_SCALE 115.2f        /* r * 1.8 (->rr) * 64 (rows per rr unit) */
#define FIDX_MAX   1022.999f     /* e <= 1022, e+1 <= 1023 */

#define NS1 148                  /* pass1 src splits: 2*148 = 296 CTAs */
#define SPMAX1 7
#define NS2 74                   /* pass2 src splits: 2*74 = 148 CTAs */
#define SPMAX2 14

#define SQRT3F      1.7320508075688772f
#define INV_SQRT3F  0.5773502691896258f
#define INV_SQRT8F  0.35355339059327373f
#define INV_SQRT32F 0.17677669529663687f
#define INV_NNF     0.031265284f          /* 1/sqrt(1023) */

/* fp16 value-only tables (16B aligned for float4 bulk copies) */
__device__ __align__(16) __half g_t1h[TABN*16];
__device__ __align__(16) __half g_t2h[TABN*64];
__device__ float g_xl [NNODES*8];
__device__ float g_sc [NNODES*32];
__device__ float g_p1 [NS1*NNODES*32];
__device__ float g_m0 [NNODES*8];
__device__ float g_m1 [NNODES*24];
__device__ float g_scv[NNODES*3];
__device__ float g_coef[NNODES*128];
__device__ float g_part[NS2*NNODES*4];

/* dynamic smem layouts */
#define SM1_TAB   (TABN*48)                      /* 49152 */
#define SM1_XL    (SM1_TAB)
#define SM1_PS    (SM1_TAB + SPMAX1*8*4)
#define SMEM1     (SM1_TAB + SPMAX1*8*4 + SPMAX1*4*4)

#define SM2_TAB   (TABN*144)                     /* 147456 */
#define SM2_CF    (SM2_TAB)
#define SM2_PS    (SM2_TAB + SPMAX2*128*4)
#define SMEM2     (SM2_TAB + SPMAX2*128*4 + SPMAX2*4*4)

__device__ __forceinline__ float siluf(float a) {
    return __fdividef(a, 1.0f + __expf(-a));
}
__device__ __forceinline__ float sigf(float a) {
    return __fdividef(1.0f, 1.0f + __expf(-a));
}

// ---------------------------------------------------------------------------
// k_prep: blocks 0..31 build the fp16 tables (32 rr-entries each);
//         blocks 32..35 do the per-node premix (node_pre).
// ---------------------------------------------------------------------------
__global__ void __launch_bounds__(256)
k_prep(const float* __restrict__ fc1_w1, const float* __restrict__ fc1_w2,
       const float* __restrict__ fc2_w1, const float* __restrict__ fc2_w2,
       const float* __restrict__ x,      const float* __restrict__ lin1a_w,
       const float* __restrict__ sc1_w)
{
    const int tid = threadIdx.x;
    const int bid = blockIdx.x;

    if (bid < 32) {
        __shared__ float w1a[1000], w1b[1000];
        __shared__ float w2a[1600];
        __shared__ float gs[32*10];
        __shared__ float h1[32*101], h2[32*101];
        const int e0 = bid * 32;

        for (int i = tid; i < 1000; i += 256) { w1a[i] = fc1_w1[i]; w1b[i] = fc2_w1[i]; }
        for (int i = tid; i < 1600; i += 256) w2a[i] = fc1_w2[i];
        for (int o = tid; o < 320; o += 256) {           /* strided: 320 > 256 */
            int e = o / 10, k = o - (o/10)*10;
            float rr = (float)(e0 + e) * (1.0f/64.0f);
            float t = rr - (float)k;
            gs[e*10 + k] = __expf(-t*t);
        }
        __syncthreads();

        for (int o = tid; o < 3200; o += 256) {
            int e = o & 31, i = o >> 5;
            float a1 = 0.f, a2 = 0.f;
#pragma unroll
            for (int k = 0; k < 10; k++) {
                float g = gs[e*10 + k];
                a1 += g * w1a[k*100 + i];
                a2 += g * w1b[k*100 + i];
            }
            h1[e*101 + i] = siluf(a1);
            h2[e*101 + i] = siluf(a2);
        }
        __syncthreads();

        for (int o = tid; o < 2560; o += 256) {
            int e = o & 31, f = o >> 5;
            int eg = e0 + e;
            float acc = 0.f;
            if (f < 16) {
#pragma unroll 4
                for (int i = 0; i < 100; i++) acc += h1[e*101 + i] * w2a[i*16 + f];
                g_t1h[eg*16 + f] = __float2half(acc * 0.1f);
            } else {
                int f2 = f - 16;
#pragma unroll 4
                for (int i = 0; i < 100; i++) acc += h2[e*101 + i] * __ldg(&fc2_w2[i*64 + f2]);
                g_t2h[eg*64 + f2] = __float2half(acc * 0.1f);
            }
        }
    } else {
        int n = (bid - 32) * 256 + tid;
        if (n >= NNODES) return;
        float xr[8];
#pragma unroll
        for (int k = 0; k < 8; k++) xr[k] = x[n*8 + k];
#pragma unroll
        for (int u = 0; u < 8; u++) {
            float a = 0.f;
#pragma unroll
            for (int k = 0; k < 8; k++) a += xr[k] * __ldg(&lin1a_w[k*8 + u]);
            g_xl[n*8 + u] = a * (INV_SQRT8F * INV_NNF);
        }
#pragma unroll
        for (int j = 0; j < 32; j++) {
            float a = 0.f;
#pragma unroll
            for (int k = 0; k < 8; k++) a += xr[k] * __ldg(&sc1_w[k*32 + j]);
            g_sc[n*32 + j] = a * INV_SQRT8F;
        }
    }
}

// ---------------------------------------------------------------------------
// Pass 1: thread = dst (512/CTA), CTA iterates its src window.
// Table (16 funcs, fp16 values, 48B-padded rows) lives in smem.
// ---------------------------------------------------------------------------
__global__ void __launch_bounds__(512)
k_pass1(const float* __restrict__ pos)
{
    extern __shared__ char sm[];
    float* sxl = (float*)(sm + SM1_XL);
    float* sps = (float*)(sm + SM1_PS);

    const int tid = threadIdx.x;
    const int d   = blockIdx.x * 512 + tid;
    const int s0  = (blockIdx.y * NNODES) / NS1;
    const int s1  = ((blockIdx.y + 1) * NNODES) / NS1;
    const int cnt = s1 - s0;

    {   /* stage table: global rows are 2 float4, smem rows are 3 (padded) */
        const float4* gt = (const float4*)g_t1h;
        float4* st = (float4*)sm;
        for (int i = tid; i < TABN*2; i += 512) {
            int row = i >> 1, u = i & 1;
            st[row*3 + u] = gt[i];
        }
    }
    for (int i = tid; i < cnt*8; i += 512) sxl[i] = g_xl[s0*8 + i];
    for (int i = tid; i < cnt*4; i += 512) {
        int j = i >> 2, c = i & 3;
        sps[i] = (c < 3) ? pos[(s0 + j)*3 + c] : 0.f;
    }
    const float pdx = pos[d*3+0], pdy = pos[d*3+1], pdz = pos[d*3+2];

    float acc[32];
#pragma unroll
    for (int q = 0; q < 32; q++) acc[q] = 0.f;
    __syncthreads();

#pragma unroll 1
    for (int j = 0; j < cnt; j++) {
        int s = s0 + j;
        float vx = sps[j*4+0] - pdx;
        float vy = sps[j*4+1] - pdy;
        float vz = sps[j*4+2] - pdz;
        float r2 = fmaxf(vx*vx + vy*vy + vz*vz, 1e-24f);
        float inv_r = rsqrtf(r2);
        float fi = fminf(r2 * inv_r * FIDX_SCALE, FIDX_MAX);
        int   e  = (int)fi;
        float t  = fi - (float)e;
        __half2 th = __floats2half2_rn(t, t);

        const float4* Te = (const float4*)(sm + e*48);
        const float4* Tf = (const float4*)(sm + e*48 + 48);
        float w[16];
#pragma unroll
        for (int q = 0; q < 2; q++) {
            float4 va = Te[q], vb = Tf[q];
            const __half2* ha = (const __half2*)&va;
            const __half2* hb = (const __half2*)&vb;
#pragma unroll
            for (int p = 0; p < 4; p++) {
                __half2 w2 = __hfma2(th, __hsub2(hb[p], ha[p]), ha[p]);
                float2 wf = __half22float2(w2);
                w[q*8 + p*2]     = wf.x;
                w[q*8 + p*2 + 1] = wf.y;
            }
        }

        float msk = (s != d) ? 1.f : 0.f;
        float sy = SQRT3F * inv_r;
        float y0 = vx*sy, y1 = vy*sy, y2 = vz*sy;

#pragma unroll
        for (int u = 0; u < 8; u++) {
            float xe = sxl[j*8 + u] * msk;
            acc[u] = fmaf(w[u], xe, acc[u]);
            float tt = w[8+u] * xe;
            acc[8 + u*3 + 0] = fmaf(tt, y0, acc[8 + u*3 + 0]);
            acc[8 + u*3 + 1] = fmaf(tt, y1, acc[8 + u*3 + 1]);
            acc[8 + u*3 + 2] = fmaf(tt, y2, acc[8 + u*3 + 2]);
        }
    }

    float* op = &g_p1[((size_t)blockIdx.y * NNODES + d) * 32];
#pragma unroll
    for (int q = 0; q < 8; q++)
        ((float4*)op)[q] = make_float4(acc[q*4], acc[q*4+1], acc[q*4+2], acc[q*4+3]);
}

// ---------------------------------------------------------------------------
__global__ void k_red1()
{
    int idx = blockIdx.x * 256 + threadIdx.x;   // 32768 total
    int d = idx >> 5, j = idx & 31;
    float s = 0.f;
#pragma unroll 4
    for (int p = 0; p < NS1; p++) s += g_p1[((size_t)p * NNODES + d)*32 + j];
    if (j < 8) g_m0[d*8 + j] = s;
    else       g_m1[d*24 + (j - 8)] = s;
}

// ---------------------------------------------------------------------------
// Node middle stage, warp-per-node: lane j owns output column j.
// ---------------------------------------------------------------------------
__global__ void __launch_bounds__(256)
k_node_mid(const float* __restrict__ lin2a0,
           const float* __restrict__ lin2a1,
           const float* __restrict__ alpha1_w,
           const float* __restrict__ sc2_w,
           const float* __restrict__ lin1b0,
           const float* __restrict__ lin1b1,
           const float* __restrict__ alpha2_w,
           const float* __restrict__ lin2b)
{
    const int lane = threadIdx.x & 31;
    const int n    = blockIdx.x * 8 + (threadIdx.x >> 5);
    const unsigned FULL = 0xffffffffu;

    /* broadcast loads of m0 (same address across warp -> 1 wavefront) */
    float m0u[8];
#pragma unroll
    for (int u = 0; u < 8; u++) m0u[u] = g_m0[n*8 + u];

    float alpha = 0.f;
#pragma unroll
    for (int u = 0; u < 8; u++) alpha = fmaf(m0u[u], __ldg(&alpha1_w[u]), alpha);
    alpha *= INV_SQRT8F;

    /* lane j: sv_j, then x0 (j<16) / gates (j>=16) */
    float o = 0.f;
#pragma unroll
    for (int u = 0; u < 8; u++) o = fmaf(m0u[u], __ldg(&lin2a0[u*32 + lane]), o);
    float sv = g_sc[n*32 + lane] + alpha * (o * INV_SQRT8F);
    float x0g = (lane < 16) ? siluf(sv) : sigf(sv);

    /* x1[v][c] in lanes v<16 */
    float gtv = __shfl_sync(FULL, x0g, 16 + (lane & 15));
    float x1c0 = 0.f, x1c1 = 0.f, x1c2 = 0.f;
    {
        float o0 = 0.f, o1 = 0.f, o2 = 0.f;
#pragma unroll
        for (int u = 0; u < 8; u++) {
            float lw = __ldg(&lin2a1[u*16 + (lane & 15)]);
            o0 = fmaf(g_m1[n*24 + u*3 + 0], lw, o0);
            o1 = fmaf(g_m1[n*24 + u*3 + 1], lw, o1);
            o2 = fmaf(g_m1[n*24 + u*3 + 2], lw, o2);
        }
        float gv = gtv * INV_SQRT8F;
        x1c0 = o0 * gv; x1c1 = o1 * gv; x1c2 = o2 * gv;
    }

    /* scv = sum_v x1[v]*sc2_w[v] * 0.25 (reduce over lanes 0..15) */
    {
        float swv = (lane < 16) ? __ldg(&sc2_w[lane]) : 0.f;
        float t0 = x1c0 * swv, t1 = x1c1 * swv, t2 = x1c2 * swv;
#pragma unroll
        for (int off = 16; off > 0; off >>= 1) {
            t0 += __shfl_xor_sync(FULL, t0, off);
            t1 += __shfl_xor_sync(FULL, t1, off);
            t2 += __shfl_xor_sync(FULL, t2, off);
        }
        if (lane == 0) {
            g_scv[n*3 + 0] = t0 * 0.25f;
            g_scv[n*3 + 1] = t1 * 0.25f;
            g_scv[n*3 + 2] = t2 * 0.25f;
        }
    }

    /* a0v (lane v<16): sum_u x0[u]*lin1b0[u][v];  x0[u] via shfl */
    float a0v = 0.f;
#pragma unroll
    for (int u = 0; u < 16; u++) {
        float xu = __shfl_sync(FULL, x0g, u);
        a0v = fmaf(xu, __ldg(&lin1b0[u*16 + (lane & 15)]), a0v);
    }
    a0v *= 0.25f;

    /* a1v (lane v<16, 3 comps): sum_u x1[u][c]*lin1b1[u][v] */
    float a1v0 = 0.f, a1v1 = 0.f, a1v2 = 0.f;
#pragma unroll
    for (int u = 0; u < 16; u++) {
        float xu0 = __shfl_sync(FULL, x1c0, u);
        float xu1 = __shfl_sync(FULL, x1c1, u);
        float xu2 = __shfl_sync(FULL, x1c2, u);
        float lw = __ldg(&lin1b1[u*16 + (lane & 15)]);
        a1v0 = fmaf(xu0, lw, a1v0);
        a1v1 = fmaf(xu1, lw, a1v1);
        a1v2 = fmaf(xu2, lw, a1v2);
    }
    a1v0 *= 0.25f; a1v1 *= 0.25f; a1v2 *= 0.25f;

    /* pass2 coefficients: [cA(16) | cQ(16) | cD(48) | cS(48)] */
    if (lane < 16) {
        const float Kc = INV_NNF * INV_SQRT32F;
        float* cf = &g_coef[n*128];
        cf[lane]      = __ldg(&alpha2_w[lane]) * a0v * Kc;
        cf[16 + lane] = __ldg(&lin2b[lane])    * a0v * Kc;
        float lw = __ldg(&lin2b[16 + lane])    * Kc;
        float aw = __ldg(&alpha2_w[16 + lane]) * Kc * INV_SQRT3F;
        cf[32 + lane*3 + 0] = lw * a1v0;
        cf[32 + lane*3 + 1] = lw * a1v1;
        cf[32 + lane*3 + 2] = lw * a1v2;
        cf[80 + lane*3 + 0] = aw * a1v0;
        cf[80 + lane*3 + 1] = aw * a1v1;
        cf[80 + lane*3 + 2] = aw * a1v2;
    }
}

// ---------------------------------------------------------------------------
// Pass 2: thread = dst (512/CTA), CTA iterates its src window.
// Table (64 funcs, fp16 values, 144B-padded rows) in smem + per-src coefs.
// ---------------------------------------------------------------------------
__global__ void __launch_bounds__(512)
k_pass2(const float* __restrict__ pos)
{
    extern __shared__ char sm[];
    float* scf = (float*)(sm + SM2_CF);
    float* sps = (float*)(sm + SM2_PS);

    const int tid = threadIdx.x;
    const int d   = blockIdx.x * 512 + tid;
    const int s0  = (blockIdx.y * NNODES) / NS2;
    const int s1  = ((blockIdx.y + 1) * NNODES) / NS2;
    const int cnt = s1 - s0;

    {   /* stage table: global rows 8 float4 -> smem rows 9 (padded) */
        const float4* gt = (const float4*)g_t2h;
        float4* st = (float4*)sm;
        for (int i = tid; i < TABN*8; i += 512) {
            int row = i >> 3, u = i & 7;
            st[row*9 + u] = gt[i];
        }
    }
    {
        const float4* cg = (const float4*)&g_coef[s0*128];
        float4* cs = (float4*)scf;
        for (int i = tid; i < cnt*32; i += 512) cs[i] = cg[i];
    }
    for (int i = tid; i < cnt*4; i += 512) {
        int j = i >> 2, c = i & 3;
        sps[i] = (c < 3) ? pos[(s0 + j)*3 + c] : 0.f;
    }
    const float pdx = pos[d*3+0], pdy = pos[d*3+1], pdz = pos[d*3+2];

    float accA = 0.f, ac0 = 0.f, ac1 = 0.f, ac2 = 0.f;
    __syncthreads();

#pragma unroll 1
    for (int j = 0; j < cnt; j++) {
        int s = s0 + j;
        float vx = sps[j*4+0] - pdx;
        float vy = sps[j*4+1] - pdy;
        float vz = sps[j*4+2] - pdz;
        float r2 = fmaxf(vx*vx + vy*vy + vz*vz, 1e-24f);
        float inv_r = rsqrtf(r2);
        float fi = fminf(r2 * inv_r * FIDX_SCALE, FIDX_MAX);
        int   e  = (int)fi;
        float t  = fi - (float)e;
        __half2 th = __floats2half2_rn(t, t);

        const float4* Te = (const float4*)(sm + e*144);
        const float4* Tf = Te + 9;
        const float*  cf = &scf[j*128];

        float A = 0.f, Q = 0.f;
        float D0 = 0.f, D1 = 0.f, D2 = 0.f;
        float S0 = 0.f, S1 = 0.f, S2 = 0.f;

#pragma unroll
        for (int q = 0; q < 8; q++) {
            float4 va = Te[q], vb = Tf[q];
            const __half2* ha = (const __half2*)&va;
            const __half2* hb = (const __half2*)&vb;
#pragma unroll
            for (int p = 0; p < 4; p++) {
                int f = q*8 + p*2;
                __half2 w2 = __hfma2(th, __hsub2(hb[p], ha[p]), ha[p]);
                float2 wf = __half22float2(w2);
                if (f < 16) {
                    A = fmaf(wf.x, cf[f], A);
                    A = fmaf(wf.y, cf[f+1], A);
                } else if (f < 32) {
                    Q = fmaf(wf.x, cf[f], Q);
                    Q = fmaf(wf.y, cf[f+1], Q);
                } else if (f < 48) {
                    int u = f - 32;
                    D0 = fmaf(wf.x, cf[32+u*3+0], D0); D0 = fmaf(wf.y, cf[32+u*3+3], D0);
                    D1 = fmaf(wf.x, cf[32+u*3+1], D1); D1 = fmaf(wf.y, cf[32+u*3+4], D1);
                    D2 = fmaf(wf.x, cf[32+u*3+2], D2); D2 = fmaf(wf.y, cf[32+u*3+5], D2);
                } else {
                    int u = f - 48;
                    S0 = fmaf(wf.x, cf[80+u*3+0], S0); S0 = fmaf(wf.y, cf[80+u*3+3], S0);
                    S1 = fmaf(wf.x, cf[80+u*3+1], S1); S1 = fmaf(wf.y, cf[80+u*3+4], S1);
                    S2 = fmaf(wf.x, cf[80+u*3+2], S2); S2 = fmaf(wf.y, cf[80+u*3+5], S2);
                }
            }
        }

        float msk = (s != d) ? 1.f : 0.f;
        float sy = SQRT3F * inv_r;
        float y0 = vx*sy, y1 = vy*sy, y2 = vz*sy;
        accA += msk * (A + y0*S0 + y1*S1 + y2*S2);
        ac0  += msk * fmaf(y0, Q, D0);
        ac1  += msk * fmaf(y1, Q, D1);
        ac2  += msk * fmaf(y2, Q, D2);
    }

    *(float4*)&g_part[((size_t)blockIdx.y * NNODES + d) * 4] =
        make_float4(accA, ac0, ac1, ac2);
}

// ---------------------------------------------------------------------------
__global__ void k_final(float* __restrict__ out)
{
    const int d = threadIdx.x;   // 1024 threads, 1 block
    float a2 = 0.f, o0 = 0.f, o1 = 0.f, o2 = 0.f;
#pragma unroll 2
    for (int p = 0; p < NS2; p++) {
        float4 v = *(const float4*)&g_part[((size_t)p * NNODES + d) * 4];
        a2 += v.x; o0 += v.y; o1 += v.z; o2 += v.w;
    }
    float n0 = g_scv[d*3 + 0] + a2 * o0;
    float n1 = g_scv[d*3 + 1] + a2 * o1;
    float n2 = g_scv[d*3 + 2] + a2 * o2;

    __shared__ float red[32*3];
#pragma unroll
    for (int o = 16; o > 0; o >>= 1) {
        n0 += __shfl_xor_sync(0xffffffffu, n0, o);
        n1 += __shfl_xor_sync(0xffffffffu, n1, o);
        n2 += __shfl_xor_sync(0xffffffffu, n2, o);
    }
    int lane = d & 31, wid = d >> 5;
    if (lane == 0) {
        red[wid*3 + 0] = n0;
        red[wid*3 + 1] = n1;
        red[wid*3 + 2] = n2;
    }
    __syncthreads();
    if (d == 0) {
        float s0 = 0.f, s1 = 0.f, s2 = 0.f;
#pragma unroll
        for (int wi = 0; wi < 32; wi++) {
            s0 += red[wi*3 + 0];
            s1 += red[wi*3 + 1];
            s2 += red[wi*3 + 2];
        }
        out[0] = s0 * (1.0f / 32.0f);
        out[1] = s1 * (1.0f / 32.0f);
        out[2] = s2 * (1.0f / 32.0f);
    }
}

// ---------------------------------------------------------------------------
extern "C" void kernel_launch(void* const* d_in, const int* in_sizes, int n_in,
                              void* d_out, int out_size)
{
    int wbase = (n_in >= 3 && in_sizes[2] > 100000) ? 4 : 2;

    const float* pos      = (const float*)d_in[0];
    const float* x        = (const float*)d_in[1];
    const float* sc1_w    = (const float*)d_in[wbase + 0];
    const float* lin1a_w  = (const float*)d_in[wbase + 1];
    const float* fc1_w1   = (const float*)d_in[wbase + 2];
    const float* fc1_w2   = (const float*)d_in[wbase + 3];
    const float* lin2a0   = (const float*)d_in[wbase + 4];
    const float* lin2a1   = (const float*)d_in[wbase + 5];
    const float* alpha1_w = (const float*)d_in[wbase + 6];
    const float* sc2_w    = (const float*)d_in[wbase + 7];
    const float* lin1b0   = (const float*)d_in[wbase + 8];
    const float* lin1b1   = (const float*)d_in[wbase + 9];
    const float* fc2_w1   = (const float*)d_in[wbase + 10];
    const float* fc2_w2   = (const float*)d_in[wbase + 11];
    const float* lin2b    = (const float*)d_in[wbase + 12];
    const float* alpha2_w = (const float*)d_in[wbase + 13];

    cudaFuncSetAttribute(k_pass1, cudaFuncAttributeMaxDynamicSharedMemorySize, SMEM1);
    cudaFuncSetAttribute(k_pass2, cudaFuncAttributeMaxDynamicSharedMemorySize, SMEM2);

    k_prep<<<36, 256>>>(fc1_w1, fc1_w2, fc2_w1, fc2_w2, x, lin1a_w, sc1_w);
    k_pass1<<<dim3(2, NS1), 512, SMEM1>>>(pos);
    k_red1<<<128, 256>>>();
    k_node_mid<<<128, 256>>>(lin2a0, lin2a1, alpha1_w, sc2_w,
                             lin1b0, lin1b1, alpha2_w, lin2b);
    k_pass2<<<dim3(2, NS2), 512, SMEM2>>>(pos);
    k_final<<<1, 1024>>>((float*)d_out);
}

// round 6
// speedup vs baseline: 3.3745x; 1.0306x over previous
#include <cuda_runtime.h>
#include <cuda_fp16.h>
#include <math.h>

#define NNODES 1024
#define TABN   768               /* rows 0..767, rr in [0,12) at 64 rows/unit */
#define FIDX_SCALE 115.2f        /* r * 1.8 * 64 */
#define FIDX_MAX   766.999f      /* e <= 766, e+1 <= 767 */

#define NS1 74                   /* pass1 src splits: grid (2,74) = 148 CTAs */
#define SPMAX1 14
#define NS2 148                  /* pass2 src splits: 148 CTAs of 1024 thr */
#define SPMAX2 7

#define SQRT3F      1.7320508075688772f
#define INV_SQRT3F  0.5773502691896258f
#define INV_SQRT8F  0.35355339059327373f
#define INV_SQRT32F 0.17677669529663687f
#define INV_NNF     0.031265284f          /* 1/sqrt(1023) */

/* fp16 value-only tables (16B aligned for float4 bulk copies) */
__device__ __align__(16) __half g_t1h[TABN*16];
__device__ __align__(16) __half g_t2h[TABN*64];
__device__ float g_xl [NNODES*8];
__device__ float g_sc [NNODES*32];
__device__ float g_p1 [NS1*NNODES*32];
__device__ float g_m0 [NNODES*8];
__device__ float g_m1 [NNODES*24];
__device__ float g_scv[NNODES*3];
__device__ float g_coef[NNODES*128];
__device__ float g_part[NS2*NNODES*4];
__device__ float g_ns  [NNODES*4];

/* dynamic smem layouts */
#define SM1_TAB   (TABN*48)                      /* 36864 */
#define SM1_XL    (SM1_TAB)
#define SM1_PS    (SM1_TAB + SPMAX1*8*4)
#define SMEM1     (SM1_PS + SPMAX1*4*4)

#define SM2_TAB   (TABN*144)                     /* 110592 */
#define SM2_CF    (SM2_TAB)
#define SM2_PS    (SM2_CF + SPMAX2*128*4)
#define SMEM2     (SM2_PS + SPMAX2*4*4)

__device__ __forceinline__ float siluf(float a) {
    return __fdividef(a, 1.0f + __expf(-a));
}
__device__ __forceinline__ float sigf(float a) {
    return __fdividef(1.0f, 1.0f + __expf(-a));
}

// ---------------------------------------------------------------------------
// k_prep: blocks 0..23 build the fp16 tables (32 rr-entries each);
//         blocks 24..27 do the per-node premix.
// ---------------------------------------------------------------------------
__global__ void __launch_bounds__(256)
k_prep(const float* __restrict__ fc1_w1, const float* __restrict__ fc1_w2,
       const float* __restrict__ fc2_w1, const float* __restrict__ fc2_w2,
       const float* __restrict__ x,      const float* __restrict__ lin1a_w,
       const float* __restrict__ sc1_w)
{
    const int tid = threadIdx.x;
    const int bid = blockIdx.x;

    if (bid < 24) {
        __shared__ float w1a[1000], w1b[1000];
        __shared__ float w2a[1600];
        __shared__ float gs[32*10];
        __shared__ float h1[32*101], h2[32*101];
        const int e0 = bid * 32;

        for (int i = tid; i < 1000; i += 256) { w1a[i] = fc1_w1[i]; w1b[i] = fc2_w1[i]; }
        for (int i = tid; i < 1600; i += 256) w2a[i] = fc1_w2[i];
        for (int o = tid; o < 320; o += 256) {           /* strided: 320 > 256 */
            int e = o / 10, k = o - (o/10)*10;
            float rr = (float)(e0 + e) * (1.0f/64.0f);
            float t = rr - (float)k;
            gs[e*10 + k] = __expf(-t*t);
        }
        __syncthreads();

        for (int o = tid; o < 3200; o += 256) {
            int e = o & 31, i = o >> 5;
            float a1 = 0.f, a2 = 0.f;
#pragma unroll
            for (int k = 0; k < 10; k++) {
                float g = gs[e*10 + k];
                a1 += g * w1a[k*100 + i];
                a2 += g * w1b[k*100 + i];
            }
            h1[e*101 + i] = siluf(a1);
            h2[e*101 + i] = siluf(a2);
        }
        __syncthreads();

        for (int o = tid; o < 2560; o += 256) {
            int e = o & 31, f = o >> 5;
            int eg = e0 + e;
            float acc = 0.f;
            if (f < 16) {
#pragma unroll 4
                for (int i = 0; i < 100; i++) acc += h1[e*101 + i] * w2a[i*16 + f];
                g_t1h[eg*16 + f] = __float2half(acc * 0.1f);
            } else {
                int f2 = f - 16;
#pragma unroll 4
                for (int i = 0; i < 100; i++) acc += h2[e*101 + i] * __ldg(&fc2_w2[i*64 + f2]);
                g_t2h[eg*64 + f2] = __float2half(acc * 0.1f);
            }
        }
    } else {
        int n = (bid - 24) * 256 + tid;
        if (n >= NNODES) return;
        float xr[8];
#pragma unroll
        for (int k = 0; k < 8; k++) xr[k] = x[n*8 + k];
#pragma unroll
        for (int u = 0; u < 8; u++) {
            float a = 0.f;
#pragma unroll
            for (int k = 0; k < 8; k++) a += xr[k] * __ldg(&lin1a_w[k*8 + u]);
            g_xl[n*8 + u] = a * (INV_SQRT8F * INV_NNF);
        }
#pragma unroll
        for (int j = 0; j < 32; j++) {
            float a = 0.f;
#pragma unroll
            for (int k = 0; k < 8; k++) a += xr[k] * __ldg(&sc1_w[k*32 + j]);
            g_sc[n*32 + j] = a * INV_SQRT8F;
        }
    }
}

// ---------------------------------------------------------------------------
// Pass 1: thread = dst (512/CTA, grid (2,74)), CTA iterates 13-14 srcs.
// Table (16 funcs fp16, 48B-padded rows) in smem.
// ---------------------------------------------------------------------------
__global__ void __launch_bounds__(512)
k_pass1(const float* __restrict__ pos)
{
    extern __shared__ char sm[];
    float* sxl = (float*)(sm + SM1_XL);
    float* sps = (float*)(sm + SM1_PS);

    const int tid = threadIdx.x;
    const int d   = blockIdx.x * 512 + tid;
    const int s0  = (blockIdx.y * NNODES) / NS1;
    const int s1  = ((blockIdx.y + 1) * NNODES) / NS1;
    const int cnt = s1 - s0;

    {   /* stage table: global rows are 2 float4, smem rows are 3 (padded) */
        const float4* gt = (const float4*)g_t1h;
        float4* st = (float4*)sm;
        for (int i = tid; i < TABN*2; i += 512) {
            int row = i >> 1, u = i & 1;
            st[row*3 + u] = gt[i];
        }
    }
    for (int i = tid; i < cnt*8; i += 512) sxl[i] = g_xl[s0*8 + i];
    for (int i = tid; i < cnt*4; i += 512) {
        int j = i >> 2, c = i & 3;
        sps[i] = (c < 3) ? pos[(s0 + j)*3 + c] : 0.f;
    }
    const float pdx = pos[d*3+0], pdy = pos[d*3+1], pdz = pos[d*3+2];

    float acc[32];
#pragma unroll
    for (int q = 0; q < 32; q++) acc[q] = 0.f;
    __syncthreads();

#pragma unroll 1
    for (int j = 0; j < cnt; j++) {
        int s = s0 + j;
        float vx = sps[j*4+0] - pdx;
        float vy = sps[j*4+1] - pdy;
        float vz = sps[j*4+2] - pdz;
        float r2 = fmaxf(vx*vx + vy*vy + vz*vz, 1e-24f);
        float inv_r = rsqrtf(r2);
        float fi = fminf(r2 * inv_r * FIDX_SCALE, FIDX_MAX);
        int   e  = (int)fi;
        float t  = fi - (float)e;
        __half2 th = __floats2half2_rn(t, t);

        const float4* Te = (const float4*)(sm + e*48);
        const float4* Tf = (const float4*)(sm + e*48 + 48);
        float w[16];
#pragma unroll
        for (int q = 0; q < 2; q++) {
            float4 va = Te[q], vb = Tf[q];
            const __half2* ha = (const __half2*)&va;
            const __half2* hb = (const __half2*)&vb;
#pragma unroll
            for (int p = 0; p < 4; p++) {
                __half2 w2 = __hfma2(th, __hsub2(hb[p], ha[p]), ha[p]);
                float2 wf = __half22float2(w2);
                w[q*8 + p*2]     = wf.x;
                w[q*8 + p*2 + 1] = wf.y;
            }
        }

        float msk = (s != d) ? 1.f : 0.f;
        float sy = SQRT3F * inv_r;
        float y0 = vx*sy, y1 = vy*sy, y2 = vz*sy;

#pragma unroll
        for (int u = 0; u < 8; u++) {
            float xe = sxl[j*8 + u] * msk;
            acc[u] = fmaf(w[u], xe, acc[u]);
            float tt = w[8+u] * xe;
            acc[8 + u*3 + 0] = fmaf(tt, y0, acc[8 + u*3 + 0]);
            acc[8 + u*3 + 1] = fmaf(tt, y1, acc[8 + u*3 + 1]);
            acc[8 + u*3 + 2] = fmaf(tt, y2, acc[8 + u*3 + 2]);
        }
    }

    float* op = &g_p1[((size_t)blockIdx.y * NNODES + d) * 32];
#pragma unroll
    for (int q = 0; q < 8; q++)
        ((float4*)op)[q] = make_float4(acc[q*4], acc[q*4+1], acc[q*4+2], acc[q*4+3]);
}

// ---------------------------------------------------------------------------
__global__ void k_red1()
{
    int idx = blockIdx.x * 256 + threadIdx.x;   // 32768 total
    int d = idx >> 5, j = idx & 31;
    float s = 0.f;
#pragma unroll 4
    for (int p = 0; p < NS1; p++) s += g_p1[((size_t)p * NNODES + d)*32 + j];
    if (j < 8) g_m0[d*8 + j] = s;
    else       g_m1[d*24 + (j - 8)] = s;
}

// ---------------------------------------------------------------------------
// Node middle stage, warp-per-node: lane j owns output column j.
// ---------------------------------------------------------------------------
__global__ void __launch_bounds__(256)
k_node_mid(const float* __restrict__ lin2a0,
           const float* __restrict__ lin2a1,
           const float* __restrict__ alpha1_w,
           const float* __restrict__ sc2_w,
           const float* __restrict__ lin1b0,
           const float* __restrict__ lin1b1,
           const float* __restrict__ alpha2_w,
           const float* __restrict__ lin2b)
{
    const int lane = threadIdx.x & 31;
    const int n    = blockIdx.x * 8 + (threadIdx.x >> 5);
    const unsigned FULL = 0xffffffffu;

    float m0u[8];
#pragma unroll
    for (int u = 0; u < 8; u++) m0u[u] = g_m0[n*8 + u];

    float alpha = 0.f;
#pragma unroll
    for (int u = 0; u < 8; u++) alpha = fmaf(m0u[u], __ldg(&alpha1_w[u]), alpha);
    alpha *= INV_SQRT8F;

    float o = 0.f;
#pragma unroll
    for (int u = 0; u < 8; u++) o = fmaf(m0u[u], __ldg(&lin2a0[u*32 + lane]), o);
    float sv = g_sc[n*32 + lane] + alpha * (o * INV_SQRT8F);
    float x0g = (lane < 16) ? siluf(sv) : sigf(sv);

    float gtv = __shfl_sync(FULL, x0g, 16 + (lane & 15));
    float x1c0 = 0.f, x1c1 = 0.f, x1c2 = 0.f;
    {
        float o0 = 0.f, o1 = 0.f, o2 = 0.f;
#pragma unroll
        for (int u = 0; u < 8; u++) {
            float lw = __ldg(&lin2a1[u*16 + (lane & 15)]);
            o0 = fmaf(g_m1[n*24 + u*3 + 0], lw, o0);
            o1 = fmaf(g_m1[n*24 + u*3 + 1], lw, o1);
            o2 = fmaf(g_m1[n*24 + u*3 + 2], lw, o2);
        }
        float gv = gtv * INV_SQRT8F;
        x1c0 = o0 * gv; x1c1 = o1 * gv; x1c2 = o2 * gv;
    }

    {
        float swv = (lane < 16) ? __ldg(&sc2_w[lane]) : 0.f;
        float t0 = x1c0 * swv, t1 = x1c1 * swv, t2 = x1c2 * swv;
#pragma unroll
        for (int off = 16; off > 0; off >>= 1) {
            t0 += __shfl_xor_sync(FULL, t0, off);
            t1 += __shfl_xor_sync(FULL, t1, off);
            t2 += __shfl_xor_sync(FULL, t2, off);
        }
        if (lane == 0) {
            g_scv[n*3 + 0] = t0 * 0.25f;
            g_scv[n*3 + 1] = t1 * 0.25f;
            g_scv[n*3 + 2] = t2 * 0.25f;
        }
    }

    float a0v = 0.f;
#pragma unroll
    for (int u = 0; u < 16; u++) {
        float xu = __shfl_sync(FULL, x0g, u);
        a0v = fmaf(xu, __ldg(&lin1b0[u*16 + (lane & 15)]), a0v);
    }
    a0v *= 0.25f;

    float a1v0 = 0.f, a1v1 = 0.f, a1v2 = 0.f;
#pragma unroll
    for (int u = 0; u < 16; u++) {
        float xu0 = __shfl_sync(FULL, x1c0, u);
        float xu1 = __shfl_sync(FULL, x1c1, u);
        float xu2 = __shfl_sync(FULL, x1c2, u);
        float lw = __ldg(&lin1b1[u*16 + (lane & 15)]);
        a1v0 = fmaf(xu0, lw, a1v0);
        a1v1 = fmaf(xu1, lw, a1v1);
        a1v2 = fmaf(xu2, lw, a1v2);
    }
    a1v0 *= 0.25f; a1v1 *= 0.25f; a1v2 *= 0.25f;

    if (lane < 16) {
        const float Kc = INV_NNF * INV_SQRT32F;
        float* cf = &g_coef[n*128];
        cf[lane]      = __ldg(&alpha2_w[lane]) * a0v * Kc;
        cf[16 + lane] = __ldg(&lin2b[lane])    * a0v * Kc;
        float lw = __ldg(&lin2b[16 + lane])    * Kc;
        float aw = __ldg(&alpha2_w[16 + lane]) * Kc * INV_SQRT3F;
        cf[32 + lane*3 + 0] = lw * a1v0;
        cf[32 + lane*3 + 1] = lw * a1v1;
        cf[32 + lane*3 + 2] = lw * a1v2;
        cf[80 + lane*3 + 0] = aw * a1v0;
        cf[80 + lane*3 + 1] = aw * a1v1;
        cf[80 + lane*3 + 2] = aw * a1v2;
    }
}

// ---------------------------------------------------------------------------
// Pass 2: thread = dst (1024/CTA, grid 148), 6-7 srcs per CTA.
// fp16 table (144B rows) in smem; chunk-order rotation by (e>>3)&1 spreads
// bank-quad classes from mod-8 to mod-16; coef loads as float4.
// ---------------------------------------------------------------------------
__global__ void __launch_bounds__(1024)
k_pass2(const float* __restrict__ pos)
{
    extern __shared__ char sm[];
    float* scf = (float*)(sm + SM2_CF);
    float* sps = (float*)(sm + SM2_PS);

    const int tid = threadIdx.x;
    const int d   = tid;
    const int s0  = (blockIdx.x * NNODES) / NS2;
    const int s1  = ((blockIdx.x + 1) * NNODES) / NS2;
    const int cnt = s1 - s0;

    {   /* stage table: global rows 8 float4 -> smem rows 9 (padded) */
        const float4* gt = (const float4*)g_t2h;
        float4* st = (float4*)sm;
        for (int i = tid; i < TABN*8; i += 1024) {
            int row = i >> 3, u = i & 7;
            st[row*9 + u] = gt[i];
        }
    }
    {
        const float4* cg = (const float4*)&g_coef[s0*128];
        float4* cs = (float4*)scf;
        for (int i = tid; i < cnt*32; i += 1024) cs[i] = cg[i];
    }
    if (tid < cnt*4) {
        int j = tid >> 2, c = tid & 3;
        sps[tid] = (c < 3) ? pos[(s0 + j)*3 + c] : 0.f;
    }
    const float pdx = pos[d*3+0], pdy = pos[d*3+1], pdz = pos[d*3+2];

    float accA = 0.f, ac0 = 0.f, ac1 = 0.f, ac2 = 0.f;
    __syncthreads();

#pragma unroll 1
    for (int j = 0; j < cnt; j++) {
        int s = s0 + j;
        float vx = sps[j*4+0] - pdx;
        float vy = sps[j*4+1] - pdy;
        float vz = sps[j*4+2] - pdz;
        float r2 = fmaxf(vx*vx + vy*vy + vz*vz, 1e-24f);
        float inv_r = rsqrtf(r2);
        float fi = fminf(r2 * inv_r * FIDX_SCALE, FIDX_MAX);
        int   e  = (int)fi;
        float t  = fi - (float)e;
        __half2 th = __floats2half2_rn(t, t);

        const char*  rowe = sm + e*144;
        const float* cf   = &scf[j*128];
        const int    rsel = (e >> 3) & 1;

        float A = 0.f, Q = 0.f;
        float D0 = 0.f, D1 = 0.f, D2 = 0.f;
        float S0 = 0.f, S1 = 0.f, S2 = 0.f;

#pragma unroll
        for (int g = 0; g < 4; g++) {
#pragma unroll
            for (int kk = 0; kk < 2; kk++) {
                const int c = (kk + rsel) & 1;       /* per-lane chunk select */
                const int q = g*2 + c;               /* funcs 8q..8q+7 */
                float4 va = *(const float4*)(rowe + q*16);
                float4 vb = *(const float4*)(rowe + 144 + q*16);
                float w[8];
                {
                    const __half2* ha = (const __half2*)&va;
                    const __half2* hb = (const __half2*)&vb;
#pragma unroll
                    for (int p = 0; p < 4; p++) {
                        __half2 w2 = __hfma2(th, __hsub2(hb[p], ha[p]), ha[p]);
                        float2 wf = __half22float2(w2);
                        w[p*2]   = wf.x;
                        w[p*2+1] = wf.y;
                    }
                }
                if (g == 0) {
                    const float4* c4 = (const float4*)(cf + q*8);
                    float4 c0 = c4[0], c1 = c4[1];
                    A += w[0]*c0.x + w[1]*c0.y + w[2]*c0.z + w[3]*c0.w
                       + w[4]*c1.x + w[5]*c1.y + w[6]*c1.z + w[7]*c1.w;
                } else if (g == 1) {
                    const float4* c4 = (const float4*)(cf + q*8);
                    float4 c0 = c4[0], c1 = c4[1];
                    Q += w[0]*c0.x + w[1]*c0.y + w[2]*c0.z + w[3]*c0.w
                       + w[4]*c1.x + w[5]*c1.y + w[6]*c1.z + w[7]*c1.w;
                } else if (g == 2) {
                    /* funcs 32..47: u0 = c*8; floats cf[32 + (u0+p)*3 + comp] */
                    const float4* c4 = (const float4*)(cf + 32 + c*24);
                    float cc[24];
#pragma unroll
                    for (int v = 0; v < 6; v++) ((float4*)cc)[v] = c4[v];
#pragma unroll
                    for (int p = 0; p < 8; p++) {
                        D0 = fmaf(w[p], cc[p*3+0], D0);
                        D1 = fmaf(w[p], cc[p*3+1], D1);
                        D2 = fmaf(w[p], cc[p*3+2], D2);
                    }
                } else {
                    const float4* c4 = (const float4*)(cf + 80 + c*24);
                    float cc[24];
#pragma unroll
                    for (int v = 0; v < 6; v++) ((float4*)cc)[v] = c4[v];
#pragma unroll
                    for (int p = 0; p < 8; p++) {
                        S0 = fmaf(w[p], cc[p*3+0], S0);
                        S1 = fmaf(w[p], cc[p*3+1], S1);
                        S2 = fmaf(w[p], cc[p*3+2], S2);
                    }
                }
            }
        }

        float msk = (s != d) ? 1.f : 0.f;
        float sy = SQRT3F * inv_r;
        float y0 = vx*sy, y1 = vy*sy, y2 = vz*sy;
        accA += msk * (A + y0*S0 + y1*S1 + y2*S2);
        ac0  += msk * fmaf(y0, Q, D0);
        ac1  += msk * fmaf(y1, Q, D1);
        ac2  += msk * fmaf(y2, Q, D2);
    }

    *(float4*)&g_part[((size_t)blockIdx.x * NNODES + d) * 4] =
        make_float4(accA, ac0, ac1, ac2);
}

// ---------------------------------------------------------------------------
__global__ void k_red2()
{
    int idx = blockIdx.x * 256 + threadIdx.x;   // 4096 total = (d, comp)
    float s = 0.f;
#pragma unroll 4
    for (int p = 0; p < NS2; p++) s += g_part[(size_t)p * (NNODES*4) + idx];
    g_ns[idx] = s;
}

// ---------------------------------------------------------------------------
__global__ void k_final(float* __restrict__ out)
{
    const int d = threadIdx.x;   // 1024 threads, 1 block
    float4 v = *(const float4*)&g_ns[d*4];
    float n0 = g_scv[d*3 + 0] + v.x * v.y;
    float n1 = g_scv[d*3 + 1] + v.x * v.z;
    float n2 = g_scv[d*3 + 2] + v.x * v.w;

    __shared__ float red[32*3];
#pragma unroll
    for (int o = 16; o > 0; o >>= 1) {
        n0 += __shfl_xor_sync(0xffffffffu, n0, o);
        n1 += __shfl_xor_sync(0xffffffffu, n1, o);
        n2 += __shfl_xor_sync(0xffffffffu, n2, o);
    }
    int lane = d & 31, wid = d >> 5;
    if (lane == 0) {
        red[wid*3 + 0] = n0;
        red[wid*3 + 1] = n1;
        red[wid*3 + 2] = n2;
    }
    __syncthreads();
    if (d == 0) {
        float s0 = 0.f, s1 = 0.f, s2 = 0.f;
#pragma unroll
        for (int wi = 0; wi < 32; wi++) {
            s0 += red[wi*3 + 0];
            s1 += red[wi*3 + 1];
            s2 += red[wi*3 + 2];
        }
        out[0] = s0 * (1.0f / 32.0f);
        out[1] = s1 * (1.0f / 32.0f);
        out[2] = s2 * (1.0f / 32.0f);
    }
}

// ---------------------------------------------------------------------------
extern "C" void kernel_launch(void* const* d_in, const int* in_sizes, int n_in,
                              void* d_out, int out_size)
{
    int wbase = (n_in >= 3 && in_sizes[2] > 100000) ? 4 : 2;

    const float* pos      = (const float*)d_in[0];
    const float* x        = (const float*)d_in[1];
    const float* sc1_w    = (const float*)d_in[wbase + 0];
    const float* lin1a_w  = (const float*)d_in[wbase + 1];
    const float* fc1_w1   = (const float*)d_in[wbase + 2];
    const float* fc1_w2   = (const float*)d_in[wbase + 3];
    const float* lin2a0   = (const float*)d_in[wbase + 4];
    const float* lin2a1   = (const float*)d_in[wbase + 5];
    const float* alpha1_w = (const float*)d_in[wbase + 6];
    const float* sc2_w    = (const float*)d_in[wbase + 7];
    const float* lin1b0   = (const float*)d_in[wbase + 8];
    const float* lin1b1   = (const float*)d_in[wbase + 9];
    const float* fc2_w1   = (const float*)d_in[wbase + 10];
    const float* fc2_w2   = (const float*)d_in[wbase + 11];
    const float* lin2b    = (const float*)d_in[wbase + 12];
    const float* alpha2_w = (const float*)d_in[wbase + 13];

    cudaFuncSetAttribute(k_pass1, cudaFuncAttributeMaxDynamicSharedMemorySize, SMEM1);
    cudaFuncSetAttribute(k_pass2, cudaFuncAttributeMaxDynamicSharedMemorySize, SMEM2);

    k_prep<<<28, 256>>>(fc1_w1, fc1_w2, fc2_w1, fc2_w2, x, lin1a_w, sc1_w);
    k_pass1<<<dim3(2, NS1), 512, SMEM1>>>(pos);
    k_red1<<<128, 256>>>();
    k_node_mid<<<128, 256>>>(lin2a0, lin2a1, alpha1_w, sc2_w,
                             lin1b0, lin1b1, alpha2_w, lin2b);
    k_pass2<<<NS2, 1024, SMEM2>>>(pos);
    k_red2<<<16, 256>>>();
    k_final<<<1, 1024>>>((float*)d_out);
}

// round 7
// speedup vs baseline: 4.8154x; 1.4270x over previous
#include <cuda_runtime.h>
#include <cuda_fp16.h>
#include <math.h>

#define NNODES 1024
#define TABN   768               /* rows 0..767, rr in [0,12) at 64 rows/unit */
#define FIDX_SCALE 115.2f        /* r * 1.8 * 64 */
#define FIDX_MAX   766.999f      /* e <= 766, e+1 <= 767 */

#define NS1 74                   /* pass1 src splits: grid (2,74) = 148 CTAs */
#define SPMAX1 14
#define NS2 148                  /* pass2: 148 CTAs of 1024 thr */
#define SPMAX2 7

#define SQRT3F      1.7320508075688772f
#define INV_SQRT3F  0.5773502691896258f
#define INV_SQRT8F  0.35355339059327373f
#define INV_SQRT32F 0.17677669529663687f
#define INV_NNF     0.031265284f          /* 1/sqrt(1023) */

/* fp16 value-only tables (16B aligned for float4 bulk copies) */
__device__ __align__(16) __half g_t1h[TABN*16];
__device__ __align__(16) __half g_t2h[TABN*64];
__device__ float g_xl [NNODES*8];
__device__ float g_sc [NNODES*32];
__device__ float g_p1 [NS1*NNODES*32];
__device__ float g_scv[NNODES*3];
__device__ float g_part[NS2*NNODES*4];
__device__ float g_ns  [NNODES*4];

/* dynamic smem layouts */
#define SM1_TAB   (TABN*48)                      /* 36864 */
#define SM1_XL    (SM1_TAB)
#define SM1_PS    (SM1_TAB + SPMAX1*8*4)
#define SMEM1     (SM1_PS + SPMAX1*4*4)

#define SM2_TAB   (TABN*144)                     /* 110592 */
#define SM2_CF    (SM2_TAB)
#define SM2_PS    (SM2_CF + SPMAX2*128*4)
#define SMEM2     (SM2_PS + SPMAX2*4*4)

__device__ __forceinline__ float siluf(float a) {
    return __fdividef(a, 1.0f + __expf(-a));
}
__device__ __forceinline__ float sigf(float a) {
    return __fdividef(1.0f, 1.0f + __expf(-a));
}

// ---------------------------------------------------------------------------
// Table build: 96 CTAs x 8 rr-entries.
// ---------------------------------------------------------------------------
__global__ void __launch_bounds__(256)
k_prep_tab(const float* __restrict__ fc1_w1, const float* __restrict__ fc1_w2,
           const float* __restrict__ fc2_w1, const float* __restrict__ fc2_w2)
{
    __shared__ float w1a[1000], w1b[1000];
    __shared__ float w2a[1600];
    __shared__ float gs[8*10];
    __shared__ float h1[8*100], h2[8*100];
    const int tid = threadIdx.x;
    const int e0  = blockIdx.x * 8;

    for (int i = tid; i < 1000; i += 256) { w1a[i] = fc1_w1[i]; w1b[i] = fc2_w1[i]; }
    for (int i = tid; i < 1600; i += 256) w2a[i] = fc1_w2[i];
    if (tid < 80) {
        int e = tid / 10, k = tid - (tid/10)*10;
        float rr = (float)(e0 + e) * (1.0f/64.0f);
        float t = rr - (float)k;
        gs[e*10 + k] = __expf(-t*t);
    }
    __syncthreads();

    for (int o = tid; o < 800; o += 256) {
        int e = o & 7, i = o >> 3;
        float a1 = 0.f, a2 = 0.f;
#pragma unroll
        for (int k = 0; k < 10; k++) {
            float g = gs[e*10 + k];
            a1 += g * w1a[k*100 + i];
            a2 += g * w1b[k*100 + i];
        }
        h1[e*100 + i] = siluf(a1);
        h2[e*100 + i] = siluf(a2);
    }
    __syncthreads();

    for (int o = tid; o < 640; o += 256) {
        int e = o / 80, f = o - (o/80)*80;
        int eg = e0 + e;
        float acc = 0.f;
        if (f < 16) {
#pragma unroll 4
            for (int i = 0; i < 100; i++) acc += h1[e*100 + i] * w2a[i*16 + f];
            g_t1h[eg*16 + f] = __float2half(acc * 0.1f);
        } else {
            int f2 = f - 16;
#pragma unroll 4
            for (int i = 0; i < 100; i++) acc += h2[e*100 + i] * __ldg(&fc2_w2[i*64 + f2]);
            g_t2h[eg*64 + f2] = __float2half(acc * 0.1f);
        }
    }
}

// ---------------------------------------------------------------------------
// Per-node premix: xl = x@lin1a/sqrt8 * inv_nn, sc = x@sc1_w/sqrt8
// ---------------------------------------------------------------------------
__global__ void __launch_bounds__(256)
k_premix(const float* __restrict__ x, const float* __restrict__ lin1a_w,
         const float* __restrict__ sc1_w)
{
    int n = blockIdx.x * 256 + threadIdx.x;
    if (n >= NNODES) return;
    float xr[8];
#pragma unroll
    for (int k = 0; k < 8; k++) xr[k] = x[n*8 + k];
#pragma unroll
    for (int u = 0; u < 8; u++) {
        float a = 0.f;
#pragma unroll
        for (int k = 0; k < 8; k++) a += xr[k] * __ldg(&lin1a_w[k*8 + u]);
        g_xl[n*8 + u] = a * (INV_SQRT8F * INV_NNF);
    }
#pragma unroll
    for (int j = 0; j < 32; j++) {
        float a = 0.f;
#pragma unroll
        for (int k = 0; k < 8; k++) a += xr[k] * __ldg(&sc1_w[k*32 + j]);
        g_sc[n*32 + j] = a * INV_SQRT8F;
    }
}

// ---------------------------------------------------------------------------
// Pass 1: thread = dst (512/CTA, grid (2,74)), CTA iterates 13-14 srcs.
// ---------------------------------------------------------------------------
__global__ void __launch_bounds__(512)
k_pass1(const float* __restrict__ pos)
{
    extern __shared__ char sm[];
    float* sxl = (float*)(sm + SM1_XL);
    float* sps = (float*)(sm + SM1_PS);

    const int tid = threadIdx.x;
    const int d   = blockIdx.x * 512 + tid;
    const int s0  = (blockIdx.y * NNODES) / NS1;
    const int s1  = ((blockIdx.y + 1) * NNODES) / NS1;
    const int cnt = s1 - s0;

    {   /* stage table: global rows are 2 float4, smem rows are 3 (padded) */
        const float4* gt = (const float4*)g_t1h;
        float4* st = (float4*)sm;
        for (int i = tid; i < TABN*2; i += 512) {
            int row = i >> 1, u = i & 1;
            st[row*3 + u] = gt[i];
        }
    }
    for (int i = tid; i < cnt*8; i += 512) sxl[i] = g_xl[s0*8 + i];
    for (int i = tid; i < cnt*4; i += 512) {
        int j = i >> 2, c = i & 3;
        sps[i] = (c < 3) ? pos[(s0 + j)*3 + c] : 0.f;
    }
    const float pdx = pos[d*3+0], pdy = pos[d*3+1], pdz = pos[d*3+2];

    float acc[32];
#pragma unroll
    for (int q = 0; q < 32; q++) acc[q] = 0.f;
    __syncthreads();

#pragma unroll 1
    for (int j = 0; j < cnt; j++) {
        int s = s0 + j;
        float vx = sps[j*4+0] - pdx;
        float vy = sps[j*4+1] - pdy;
        float vz = sps[j*4+2] - pdz;
        float r2 = fmaxf(vx*vx + vy*vy + vz*vz, 1e-24f);
        float inv_r = rsqrtf(r2);
        float fi = fminf(r2 * inv_r * FIDX_SCALE, FIDX_MAX);
        int   e  = (int)fi;
        float t  = fi - (float)e;
        __half2 th = __floats2half2_rn(t, t);

        const float4* Te = (const float4*)(sm + e*48);
        const float4* Tf = (const float4*)(sm + e*48 + 48);
        float w[16];
#pragma unroll
        for (int q = 0; q < 2; q++) {
            float4 va = Te[q], vb = Tf[q];
            const __half2* ha = (const __half2*)&va;
            const __half2* hb = (const __half2*)&vb;
#pragma unroll
            for (int p = 0; p < 4; p++) {
                __half2 w2 = __hfma2(th, __hsub2(hb[p], ha[p]), ha[p]);
                float2 wf = __half22float2(w2);
                w[q*8 + p*2]     = wf.x;
                w[q*8 + p*2 + 1] = wf.y;
            }
        }

        float msk = (s != d) ? 1.f : 0.f;
        float sy = SQRT3F * inv_r;
        float y0 = vx*sy, y1 = vy*sy, y2 = vz*sy;

#pragma unroll
        for (int u = 0; u < 8; u++) {
            float xe = sxl[j*8 + u] * msk;
            acc[u] = fmaf(w[u], xe, acc[u]);
            float tt = w[8+u] * xe;
            acc[8 + u*3 + 0] = fmaf(tt, y0, acc[8 + u*3 + 0]);
            acc[8 + u*3 + 1] = fmaf(tt, y1, acc[8 + u*3 + 1]);
            acc[8 + u*3 + 2] = fmaf(tt, y2, acc[8 + u*3 + 2]);
        }
    }

    float* op = &g_p1[((size_t)blockIdx.y * NNODES + d) * 32];
#pragma unroll
    for (int q = 0; q < 8; q++)
        ((float4*)op)[q] = make_float4(acc[q*4], acc[q*4+1], acc[q*4+2], acc[q*4+3]);
}

// ---------------------------------------------------------------------------
// Pass 2 FUSED: warps 0..cnt-1 do red1 + node_mid for this CTA's srcs
// (coef straight into smem) while remaining warps stage the table. Then
// all 1024 threads run the pair loop (thread = dst).
// ---------------------------------------------------------------------------
__global__ void __launch_bounds__(1024)
k_pass2(const float* __restrict__ pos,
        const float* __restrict__ lin2a0,
        const float* __restrict__ lin2a1,
        const float* __restrict__ alpha1_w,
        const float* __restrict__ sc2_w,
        const float* __restrict__ lin1b0,
        const float* __restrict__ lin1b1,
        const float* __restrict__ alpha2_w,
        const float* __restrict__ lin2b)
{
    extern __shared__ char sm[];
    float* scf = (float*)(sm + SM2_CF);
    float* sps = (float*)(sm + SM2_PS);

    const int tid = threadIdx.x;
    const int d   = tid;
    const int s0  = (blockIdx.x * NNODES) / NS2;
    const int s1  = ((blockIdx.x + 1) * NNODES) / NS2;
    const int cnt = s1 - s0;
    const int wid = tid >> 5;
    const int lane = tid & 31;
    const unsigned FULL = 0xffffffffu;

    if (wid < cnt) {
        /* ---- red1 + node_mid for node n = s0 + wid ---- */
        const int n = s0 + wid;
        float mval = 0.f;
#pragma unroll 4
        for (int p = 0; p < NS1; p++)
            mval += g_p1[((size_t)p * NNODES + n)*32 + lane];

        float m0u[8];
#pragma unroll
        for (int u = 0; u < 8; u++) m0u[u] = __shfl_sync(FULL, mval, u);

        float alpha = 0.f;
#pragma unroll
        for (int u = 0; u < 8; u++) alpha = fmaf(m0u[u], __ldg(&alpha1_w[u]), alpha);
        alpha *= INV_SQRT8F;

        float o = 0.f;
#pragma unroll
        for (int u = 0; u < 8; u++) o = fmaf(m0u[u], __ldg(&lin2a0[u*32 + lane]), o);
        float sv = g_sc[n*32 + lane] + alpha * (o * INV_SQRT8F);
        float x0g = (lane < 16) ? siluf(sv) : sigf(sv);

        float gtv = __shfl_sync(FULL, x0g, 16 + (lane & 15));
        float x1c0, x1c1, x1c2;
        {
            float o0 = 0.f, o1 = 0.f, o2 = 0.f;
#pragma unroll
            for (int u = 0; u < 8; u++) {
                float lw = __ldg(&lin2a1[u*16 + (lane & 15)]);
                o0 = fmaf(__shfl_sync(FULL, mval, 8 + u*3 + 0), lw, o0);
                o1 = fmaf(__shfl_sync(FULL, mval, 8 + u*3 + 1), lw, o1);
                o2 = fmaf(__shfl_sync(FULL, mval, 8 + u*3 + 2), lw, o2);
            }
            float gv = gtv * INV_SQRT8F;
            x1c0 = o0 * gv; x1c1 = o1 * gv; x1c2 = o2 * gv;
        }

        {
            float swv = (lane < 16) ? __ldg(&sc2_w[lane]) : 0.f;
            float t0 = x1c0 * swv, t1 = x1c1 * swv, t2 = x1c2 * swv;
#pragma unroll
            for (int off = 16; off > 0; off >>= 1) {
                t0 += __shfl_xor_sync(FULL, t0, off);
                t1 += __shfl_xor_sync(FULL, t1, off);
                t2 += __shfl_xor_sync(FULL, t2, off);
            }
            if (lane == 0) {
                g_scv[n*3 + 0] = t0 * 0.25f;
                g_scv[n*3 + 1] = t1 * 0.25f;
                g_scv[n*3 + 2] = t2 * 0.25f;
            }
        }

        float a0v = 0.f;
#pragma unroll
        for (int u = 0; u < 16; u++) {
            float xu = __shfl_sync(FULL, x0g, u);
            a0v = fmaf(xu, __ldg(&lin1b0[u*16 + (lane & 15)]), a0v);
        }
        a0v *= 0.25f;

        float a1v0 = 0.f, a1v1 = 0.f, a1v2 = 0.f;
#pragma unroll
        for (int u = 0; u < 16; u++) {
            float xu0 = __shfl_sync(FULL, x1c0, u);
            float xu1 = __shfl_sync(FULL, x1c1, u);
            float xu2 = __shfl_sync(FULL, x1c2, u);
            float lw = __ldg(&lin1b1[u*16 + (lane & 15)]);
            a1v0 = fmaf(xu0, lw, a1v0);
            a1v1 = fmaf(xu1, lw, a1v1);
            a1v2 = fmaf(xu2, lw, a1v2);
        }
        a1v0 *= 0.25f; a1v1 *= 0.25f; a1v2 *= 0.25f;

        if (lane < 16) {
            const float Kc = INV_NNF * INV_SQRT32F;
            float* cf = &scf[wid*128];
            cf[lane]      = __ldg(&alpha2_w[lane]) * a0v * Kc;
            cf[16 + lane] = __ldg(&lin2b[lane])    * a0v * Kc;
            float lw = __ldg(&lin2b[16 + lane])    * Kc;
            float aw = __ldg(&alpha2_w[16 + lane]) * Kc * INV_SQRT3F;
            cf[32 + lane*3 + 0] = lw * a1v0;
            cf[32 + lane*3 + 1] = lw * a1v1;
            cf[32 + lane*3 + 2] = lw * a1v2;
            cf[80 + lane*3 + 0] = aw * a1v0;
            cf[80 + lane*3 + 1] = aw * a1v1;
            cf[80 + lane*3 + 2] = aw * a1v2;
        }
    } else {
        /* ---- staging warps: table + src positions ---- */
        const int stid = tid - cnt*32;
        const int nst  = 1024 - cnt*32;
        const float4* gt = (const float4*)g_t2h;
        float4* st = (float4*)sm;
        for (int i = stid; i < TABN*8; i += nst) {
            int row = i >> 3, u = i & 7;
            st[row*9 + u] = gt[i];
        }
        if (stid < cnt*4) {
            int j = stid >> 2, c = stid & 3;
            sps[stid] = (c < 3) ? pos[(s0 + j)*3 + c] : 0.f;
        }
    }

    const float pdx = pos[d*3+0], pdy = pos[d*3+1], pdz = pos[d*3+2];
    float accA = 0.f, ac0 = 0.f, ac1 = 0.f, ac2 = 0.f;
    __syncthreads();

#pragma unroll 1
    for (int j = 0; j < cnt; j++) {
        int s = s0 + j;
        float vx = sps[j*4+0] - pdx;
        float vy = sps[j*4+1] - pdy;
        float vz = sps[j*4+2] - pdz;
        float r2 = fmaxf(vx*vx + vy*vy + vz*vz, 1e-24f);
        float inv_r = rsqrtf(r2);
        float fi = fminf(r2 * inv_r * FIDX_SCALE, FIDX_MAX);
        int   e  = (int)fi;
        float t  = fi - (float)e;
        __half2 th = __floats2half2_rn(t, t);

        const char*  rowe = sm + e*144;
        const float* cf   = &scf[j*128];

        float A = 0.f, Q = 0.f;
        float D0 = 0.f, D1 = 0.f, D2 = 0.f;
        float S0 = 0.f, S1 = 0.f, S2 = 0.f;

#pragma unroll
        for (int q = 0; q < 8; q++) {
            float4 va = *(const float4*)(rowe + q*16);
            float4 vb = *(const float4*)(rowe + 144 + q*16);
            float w[8];
            {
                const __half2* ha = (const __half2*)&va;
                const __half2* hb = (const __half2*)&vb;
#pragma unroll
                for (int p = 0; p < 4; p++) {
                    __half2 w2 = __hfma2(th, __hsub2(hb[p], ha[p]), ha[p]);
                    float2 wf = __half22float2(w2);
                    w[p*2]   = wf.x;
                    w[p*2+1] = wf.y;
                }
            }
            if (q < 2) {
                const float4* c4 = (const float4*)(cf + q*8);
                float4 c0 = c4[0], c1 = c4[1];
                A += w[0]*c0.x + w[1]*c0.y + w[2]*c0.z + w[3]*c0.w
                   + w[4]*c1.x + w[5]*c1.y + w[6]*c1.z + w[7]*c1.w;
            } else if (q < 4) {
                const float4* c4 = (const float4*)(cf + q*8);
                float4 c0 = c4[0], c1 = c4[1];
                Q += w[0]*c0.x + w[1]*c0.y + w[2]*c0.z + w[3]*c0.w
                   + w[4]*c1.x + w[5]*c1.y + w[6]*c1.z + w[7]*c1.w;
            } else if (q < 6) {
                const float4* c4 = (const float4*)(cf + 32 + (q-4)*24);
                float cc[24];
#pragma unroll
                for (int v = 0; v < 6; v++) ((float4*)cc)[v] = c4[v];
#pragma unroll
                for (int p = 0; p < 8; p++) {
                    D0 = fmaf(w[p], cc[p*3+0], D0);
                    D1 = fmaf(w[p], cc[p*3+1], D1);
                    D2 = fmaf(w[p], cc[p*3+2], D2);
                }
            } else {
                const float4* c4 = (const float4*)(cf + 80 + (q-6)*24);
                float cc[24];
#pragma unroll
                for (int v = 0; v < 6; v++) ((float4*)cc)[v] = c4[v];
#pragma unroll
                for (int p = 0; p < 8; p++) {
                    S0 = fmaf(w[p], cc[p*3+0], S0);
                    S1 = fmaf(w[p], cc[p*3+1], S1);
                    S2 = fmaf(w[p], cc[p*3+2], S2);
                }
            }
        }

        float msk = (s != d) ? 1.f : 0.f;
        float sy = SQRT3F * inv_r;
        float y0 = vx*sy, y1 = vy*sy, y2 = vz*sy;
        accA += msk * (A + y0*S0 + y1*S1 + y2*S2);
        ac0  += msk * fmaf(y0, Q, D0);
        ac1  += msk * fmaf(y1, Q, D1);
        ac2  += msk * fmaf(y2, Q, D2);
    }

    *(float4*)&g_part[((size_t)blockIdx.x * NNODES + d) * 4] =
        make_float4(accA, ac0, ac1, ac2);
}

// ---------------------------------------------------------------------------
__global__ void k_red2()
{
    int idx = blockIdx.x * 256 + threadIdx.x;   // 4096 total = (d, comp)
    float s = 0.f;
#pragma unroll 4
    for (int p = 0; p < NS2; p++) s += g_part[(size_t)p * (NNODES*4) + idx];
    g_ns[idx] = s;
}

// ---------------------------------------------------------------------------
__global__ void k_final(float* __restrict__ out)
{
    const int d = threadIdx.x;   // 1024 threads, 1 block
    float4 v = *(const float4*)&g_ns[d*4];
    float n0 = g_scv[d*3 + 0] + v.x * v.y;
    float n1 = g_scv[d*3 + 1] + v.x * v.z;
    float n2 = g_scv[d*3 + 2] + v.x * v.w;

    __shared__ float red[32*3];
#pragma unroll
    for (int o = 16; o > 0; o >>= 1) {
        n0 += __shfl_xor_sync(0xffffffffu, n0, o);
        n1 += __shfl_xor_sync(0xffffffffu, n1, o);
        n2 += __shfl_xor_sync(0xffffffffu, n2, o);
    }
    int lane = d & 31, wid = d >> 5;
    if (lane == 0) {
        red[wid*3 + 0] = n0;
        red[wid*3 + 1] = n1;
        red[wid*3 + 2] = n2;
    }
    __syncthreads();
    if (d == 0) {
        float s0 = 0.f, s1 = 0.f, s2 = 0.f;
#pragma unroll
        for (int wi = 0; wi < 32; wi++) {
            s0 += red[wi*3 + 0];
            s1 += red[wi*3 + 1];
            s2 += red[wi*3 + 2];
        }
        out[0] = s0 * (1.0f / 32.0f);
        out[1] = s1 * (1.0f / 32.0f);
        out[2] = s2 * (1.0f / 32.0f);
    }
}

// ---------------------------------------------------------------------------
extern "C" void kernel_launch(void* const* d_in, const int* in_sizes, int n_in,
                              void* d_out, int out_size)
{
    int wbase = (n_in >= 3 && in_sizes[2] > 100000) ? 4 : 2;

    const float* pos      = (const float*)d_in[0];
    const float* x        = (const float*)d_in[1];
    const float* sc1_w    = (const float*)d_in[wbase + 0];
    const float* lin1a_w  = (const float*)d_in[wbase + 1];
    const float* fc1_w1   = (const float*)d_in[wbase + 2];
    const float* fc1_w2   = (const float*)d_in[wbase + 3];
    const float* lin2a0   = (const float*)d_in[wbase + 4];
    const float* lin2a1   = (const float*)d_in[wbase + 5];
    const float* alpha1_w = (const float*)d_in[wbase + 6];
    const float* sc2_w    = (const float*)d_in[wbase + 7];
    const float* lin1b0   = (const float*)d_in[wbase + 8];
    const float* lin1b1   = (const float*)d_in[wbase + 9];
    const float* fc2_w1   = (const float*)d_in[wbase + 10];
    const float* fc2_w2   = (const float*)d_in[wbase + 11];
    const float* lin2b    = (const float*)d_in[wbase + 12];
    const float* alpha2_w = (const float*)d_in[wbase + 13];

    cudaFuncSetAttribute(k_pass1, cudaFuncAttributeMaxDynamicSharedMemorySize, SMEM1);
    cudaFuncSetAttribute(k_pass2, cudaFuncAttributeMaxDynamicSharedMemorySize, SMEM2);

    k_prep_tab<<<96, 256>>>(fc1_w1, fc1_w2, fc2_w1, fc2_w2);
    k_premix<<<4, 256>>>(x, lin1a_w, sc1_w);
    k_pass1<<<dim3(2, NS1), 512, SMEM1>>>(pos);
    k_pass2<<<NS2, 1024, SMEM2>>>(pos, lin2a0, lin2a1, alpha1_w, sc2_w,
                                  lin1b0, lin1b1, alpha2_w, lin2b);
    k_red2<<<16, 256>>>();
    k_final<<<1, 1024>>>((float*)d_out);
}